// round 3
// baseline (speedup 1.0000x reference)
#include <cuda_runtime.h>
#include <cuda_bf16.h>
#include <math.h>

// ---------------- problem dims (fixed) ----------------
#define S_ 4
#define K_ 50
#define T_ 25
#define R_ 128
#define V_ 10000
#define TH_ 800
#define EH_ 200
#define B_ 128
#define DELTA_ 0.005

#define ACC_KLA 0
#define ACC_KLE 1
#define ACC_KLT 2
#define ACC_NLL 3

// ---------------- device scratch ----------------
__device__ double g_acc[8];
__device__ float  g_xpre[T_ * EH_];
__device__ float  g_gx[T_ * 4 * EH_];
__device__ float  g_c0[4 * EH_];
__device__ float  g_hseq[T_ * EH_];
__device__ float  g_proj[T_ * 100];
__device__ float  g_etas[T_ * K_];
__device__ float  g_h1pre[B_ * TH_];
__device__ float  g_h1[B_ * TH_];
__device__ float  g_h2pre[B_ * TH_];
__device__ float  g_h2[B_ * TH_];
__device__ float  g_mu[B_ * K_];
__device__ float  g_ls[B_ * K_];
__device__ float  g_theta[B_ * K_];
__device__ float  g_alpha0[T_ * K_ * R_];
__device__ float  g_logits[T_ * K_ * V_];   // holds exp(logit)
__device__ float  g_sumexp[T_ * K_];
__device__ float  g_gates[2][4 * EH_];
__device__ int    g_tcount[T_];
__device__ int    g_tdocs[T_ * B_];

__device__ __forceinline__ float sigf(float x) { return 1.f / (1.f + __expf(-x)); }

// ================= k_prep: zero + alpha0 transpose + tlist + c0 =================
__global__ void k_prep(const int* __restrict__ times, const float* __restrict__ Wih,
                       const float* __restrict__ emb, const float* __restrict__ bih,
                       const float* __restrict__ bhh, const float* __restrict__ mu) {
    int blk = blockIdx.x, tid = threadIdx.x;
    if (blk == 0) {
        if (tid < 8) g_acc[tid] = 0.0;
        if (tid < T_) g_tcount[tid] = 0;
        for (int i = tid; i < T_ * K_; i += 256) g_sumexp[i] = 0.f;
        for (int i = tid; i < T_ * EH_; i += 256) g_xpre[i] = 0.f;
        __syncthreads();
        if (tid < B_) {
            int t = times[tid];
            int p = atomicAdd(&g_tcount[t], 1);
            g_tdocs[t * B_ + p] = tid;
        }
    } else if (blk < 32) {
        for (int idx = (blk - 1) * 256 + tid; idx < T_ * K_ * R_; idx += 31 * 256) {
            int r = idx % R_;
            int k = (idx / R_) % K_;
            int t = idx / (R_ * K_);
            g_alpha0[idx] = mu[(k * T_ + t) * R_ + r];
        }
        for (int idx = (blk - 1) * 256 + tid; idx < B_ * TH_; idx += 31 * 256) {
            g_h1pre[idx] = 0.f;
            g_h2pre[idx] = 0.f;
        }
    } else {
        int w = (blk - 32) * 8 + (tid >> 5), lane = tid & 31;
        for (int g = w; g < 4 * EH_; g += 64) {
            const float* row = Wih + g * EH_;
            float s = 0.f;
            for (int e = lane; e < EH_; e += 32) s += row[e] * emb[e];
            for (int o = 16; o; o >>= 1) s += __shfl_xor_sync(0xffffffffu, s, o);
            if (lane == 0) g_c0[g] = s + bih[g] + bhh[g];
        }
    }
}

// ================= kl_alpha (inline 4x4 slogdet) =================
__global__ __launch_bounds__(256) void k_klalpha(const float* __restrict__ mu,
                                                 const float* __restrict__ ls,
                                                 const float* __restrict__ slc) {
    __shared__ double pst[10];   // ld_p0, ld_pt, d_p0[4], d_pt[4]
    if (threadIdx.x == 0) {
        double M0[4][4], Mt[4][4];
        for (int i = 0; i < 4; i++)
            for (int j = 0; j < 4; j++) {
                double v = (double)slc[i * 4 + j];
                M0[i][j] = exp(v);
                Mt[i][j] = DELTA_ * v;
            }
        for (int which = 0; which < 2; which++) {
            double lu[4][4];
            for (int i = 0; i < 4; i++)
                for (int j = 0; j < 4; j++) lu[i][j] = which ? Mt[i][j] : M0[i][j];
            double ld = 0.0;
            for (int i = 0; i < 4; i++) {
                int p = i;
                for (int r = i + 1; r < 4; r++)
                    if (fabs(lu[r][i]) > fabs(lu[p][i])) p = r;
                if (p != i)
                    for (int c = 0; c < 4; c++) { double t = lu[i][c]; lu[i][c] = lu[p][c]; lu[p][c] = t; }
                ld += log(fabs(lu[i][i]));
                for (int r = i + 1; r < 4; r++) {
                    double f = lu[r][i] / lu[i][i];
                    for (int c = i; c < 4; c++) lu[r][c] -= f * lu[i][c];
                }
            }
            pst[which] = ld;
        }
        for (int s = 0; s < 4; s++) { pst[2 + s] = M0[s][s]; pst[6 + s] = Mt[s][s]; }
    }
    __syncthreads();
    int idx = blockIdx.x * blockDim.x + threadIdx.x;
    double term = 0.0;
    if (idx < K_ * T_ * R_) {
        int r = idx % R_;
        int t = (idx / R_) % T_;
        int k = idx / (R_ * T_);
        double ldp = (t == 0) ? pst[0] : pst[1];
        const double* dp = (t == 0) ? (pst + 2) : (pst + 6);
        double ldq = 0.0, tr = 0.0, quad = 0.0;
        for (int s = 0; s < 4; s++) {
            int off = ((s * K_ + k) * T_ + t) * R_ + r;
            float lsv = ls[off];
            float inv = __expf(-lsv);
            ldq += (double)lsv;
            tr += dp[s] * (double)inv;
            float m = mu[off];
            float d = (t == 0) ? m : (m - mu[off - R_]);
            quad += (double)(d * d) * (double)inv;
        }
        term = ldq - ldp - 4.0 + tr + quad;
    }
    __shared__ double red[256];
    int tid = threadIdx.x;
    red[tid] = term;
    __syncthreads();
    for (int o = 128; o; o >>= 1) {
        if (tid < o) red[tid] += red[tid + o];
        __syncthreads();
    }
    if (tid == 0) atomicAdd(&g_acc[ACC_KLA], red[0]);
}

// ================= 128x128x8 SGEMM (NT), 8x8 per thread, reg-prefetch =================
// C[m,n] (+)= sum_k A[m*lda+k]*B[n*ldb+k]; optional bias[n] (store mode), optional
// exp-store + per-row expsum accumulation (store mode, splitK==1).
__global__ __launch_bounds__(256, 2) void gemm128(
    const float* __restrict__ A, int lda,
    const float* __restrict__ B, int ldb,
    float* __restrict__ C, int M, int N, int K,
    const float* __restrict__ bias, float* __restrict__ expsum, int atomic_out)
{
    __shared__ float As[8][132];
    __shared__ float Bs[8][132];
    int tid = threadIdx.x;
    int tx = tid & 15, ty = tid >> 4;
    int m0 = blockIdx.x * 128, n0 = blockIdx.y * 128;
    int splitK = gridDim.z;
    int kc = ((K + splitK - 1) / splitK + 7) & ~7;
    int kbeg = blockIdx.z * kc;
    int kend = min(K, kbeg + kc);
    if (kbeg >= kend) return;
    int lr = tid >> 1;
    int lk = (tid & 1) * 4;
    bool mok = (m0 + lr) < M;
    bool nok = (n0 + lr) < N;
    const float* Ar = A + (size_t)(m0 + lr) * lda;
    const float* Br = B + (size_t)(n0 + lr) * ldb;
    float2 pa0, pa1, pb0, pb1;
    {
        int kg = kbeg + lk;
        float2 z = make_float2(0.f, 0.f);
        pa0 = mok ? *(const float2*)(Ar + kg) : z;
        pa1 = mok ? *(const float2*)(Ar + kg + 2) : z;
        pb0 = nok ? *(const float2*)(Br + kg) : z;
        pb1 = nok ? *(const float2*)(Br + kg + 2) : z;
    }
    float acc[8][8];
#pragma unroll
    for (int i = 0; i < 8; i++)
#pragma unroll
        for (int j = 0; j < 8; j++) acc[i][j] = 0.f;

    for (int k0 = kbeg; k0 < kend; k0 += 8) {
        As[lk + 0][lr] = pa0.x; As[lk + 1][lr] = pa0.y; As[lk + 2][lr] = pa1.x; As[lk + 3][lr] = pa1.y;
        Bs[lk + 0][lr] = pb0.x; Bs[lk + 1][lr] = pb0.y; Bs[lk + 2][lr] = pb1.x; Bs[lk + 3][lr] = pb1.y;
        __syncthreads();
        int kn = k0 + 8;
        if (kn < kend) {
            int kg = kn + lk;
            float2 z = make_float2(0.f, 0.f);
            pa0 = mok ? *(const float2*)(Ar + kg) : z;
            pa1 = mok ? *(const float2*)(Ar + kg + 2) : z;
            pb0 = nok ? *(const float2*)(Br + kg) : z;
            pb1 = nok ? *(const float2*)(Br + kg + 2) : z;
        }
#pragma unroll
        for (int kk = 0; kk < 8; kk++) {
            float4 a4 = *(const float4*)&As[kk][ty * 8];
            float4 a5 = *(const float4*)&As[kk][ty * 8 + 4];
            float4 b4 = *(const float4*)&Bs[kk][tx * 8];
            float4 b5 = *(const float4*)&Bs[kk][tx * 8 + 4];
            float a[8] = {a4.x, a4.y, a4.z, a4.w, a5.x, a5.y, a5.z, a5.w};
            float b[8] = {b4.x, b4.y, b4.z, b4.w, b5.x, b5.y, b5.z, b5.w};
#pragma unroll
            for (int i = 0; i < 8; i++)
#pragma unroll
                for (int j = 0; j < 8; j++) acc[i][j] = fmaf(a[i], b[j], acc[i][j]);
        }
        __syncthreads();
    }

    int lane = tid & 31;
#pragma unroll
    for (int i = 0; i < 8; i++) {
        int m = m0 + ty * 8 + i;
        if (m >= M) continue;
        float vrow[8];
#pragma unroll
        for (int j = 0; j < 8; j++) {
            float v = acc[i][j];
            int n = n0 + tx * 8 + j;
            if (bias && n < N) v += bias[n];
            vrow[j] = v;
        }
        if (expsum) {
            float rs = 0.f;
#pragma unroll
            for (int j = 0; j < 8; j++) {
                int n = n0 + tx * 8 + j;
                float e = (n < N) ? __expf(vrow[j]) : 0.f;
                vrow[j] = e;
                rs += e;
            }
            for (int o = 8; o; o >>= 1) rs += __shfl_xor_sync(0xffffffffu, rs, o);
            if ((lane & 15) == 0) atomicAdd(&expsum[m], rs);
        }
        float* crow = C + (size_t)m * N;
        int n = n0 + tx * 8;
        if (atomic_out) {
#pragma unroll
            for (int j = 0; j < 8; j++)
                if (n + j < N) atomicAdd(&crow[n + j], vrow[j]);
        } else {
            if (n + 7 < N) {
                *(float4*)&crow[n] = make_float4(vrow[0], vrow[1], vrow[2], vrow[3]);
                *(float4*)&crow[n + 4] = make_float4(vrow[4], vrow[5], vrow[6], vrow[7]);
            } else {
                for (int j = 0; j < 8; j++)
                    if (n + j < N) crow[n + j] = vrow[j];
            }
        }
    }
}

// ================= LSTM recurrence: 8-CTA cluster, Whh persistent in SMEM =================
__global__ __cluster_dims__(8, 1, 1) __launch_bounds__(256)
void k_lstm(const float* __restrict__ Whh) {
    extern __shared__ float sm[];
    float* sW = sm;                 // 100*200
    float* h  = sm + 100 * EH_;     // 200
    float* c  = h + EH_;            // 200
    int tid = threadIdx.x;
    int blk = blockIdx.x;
    int g0 = blk * 100;
    for (int i = tid; i < 100 * EH_; i += 256) sW[i] = Whh[g0 * EH_ + i];
    for (int i = tid; i < EH_; i += 256) { h[i] = 0.f; c[i] = 0.f; }
    __syncthreads();
    int w = tid >> 5, lane = tid & 31;
    for (int t = 0; t < T_; t++) {
        const float* gx = g_gx + t * 4 * EH_ + g0;
        float* gout = g_gates[t & 1];
        for (int g = w; g < 100; g += 8) {
            const float* row = sW + g * EH_;
            float s = 0.f;
            for (int e = lane; e < EH_; e += 32) s += row[e] * h[e];
            for (int o = 16; o; o >>= 1) s += __shfl_xor_sync(0xffffffffu, s, o);
            if (lane == 0) gout[g0 + g] = s + gx[g];
        }
        __threadfence();
        asm volatile("barrier.cluster.arrive.aligned;" ::: "memory");
        asm volatile("barrier.cluster.wait.aligned;" ::: "memory");
        const volatile float* gb = g_gates[t & 1];
        for (int e = tid; e < EH_; e += 256) {
            float iv = gb[e], fv = gb[EH_ + e], gg = gb[2 * EH_ + e], ov = gb[3 * EH_ + e];
            float cc = sigf(fv) * c[e] + sigf(iv) * tanhf(gg);
            c[e] = cc;
            float hh = sigf(ov) * tanhf(cc);
            h[e] = hh;
            if (blk == 0) g_hseq[t * EH_ + e] = hh;
        }
        __syncthreads();
    }
}

// ================= eta projection (parallel over t): proj = W[:, :200] @ h_t + b =================
__global__ __launch_bounds__(128) void k_etaproj(const float* __restrict__ Wm, const float* __restrict__ bm,
                                                 const float* __restrict__ Wl, const float* __restrict__ bl) {
    int t = blockIdx.x;
    int w = threadIdx.x >> 5, lane = threadIdx.x & 31;
    const float* hrow = g_hseq + t * EH_;
    for (int o = w; o < 100; o += 4) {
        const float* row = (o < 50) ? (Wm + o * (EH_ + K_)) : (Wl + (o - 50) * (EH_ + K_));
        float s = 0.f;
        for (int e = lane; e < EH_; e += 32) s += row[e] * hrow[e];
        for (int off = 16; off; off >>= 1) s += __shfl_xor_sync(0xffffffffu, s, off);
        if (lane == 0) g_proj[t * 100 + o] = s + ((o < 50) ? bm[o] : bl[o - 50]);
    }
}

// ================= eta scan (tiny, only the 50-wide recurrent part) =================
__global__ __launch_bounds__(128) void k_etascan(const float* __restrict__ Wm,
                                                 const float* __restrict__ Wl) {
    __shared__ float sWe[100 * 53];
    __shared__ float eprev[52];
    __shared__ float val[128];
    __shared__ double red[64];
    int tid = threadIdx.x;
    for (int i = tid; i < 100 * 50; i += 128) {
        int r = i / 50, j = i % 50;
        sWe[r * 53 + j] = (r < 50) ? Wm[r * (EH_ + K_) + EH_ + j]
                                   : Wl[(r - 50) * (EH_ + K_) + EH_ + j];
    }
    if (tid < 50) eprev[tid] = 0.f;
    __syncthreads();
    double klacc = 0.0;
    const float LOG_DELTA = logf((float)DELTA_);
    for (int t = 0; t < T_; t++) {
        float acc = 0.f;
        if (tid < 100) {
            acc = g_proj[t * 100 + tid];
            const float* row = &sWe[tid * 53];
#pragma unroll
            for (int j = 0; j < 50; j++) acc = fmaf(row[j], eprev[j], acc);
        }
        val[tid] = acc;
        __syncthreads();
        double kl = 0.0;
        float mu = 0.f;
        if (tid < 50) {
            mu = val[tid];
            float lsv = val[50 + tid];
            float ep = eprev[tid];
            float pls = (t == 0) ? 0.f : LOG_DELTA;
            float den = ((t == 0) ? 1.0f : (float)DELTA_) + 1e-6f;
            float d = mu - ep;
            kl = 0.5 * ((double)((__expf(lsv) + d * d) / den) - 1.0 + (double)pls - (double)lsv);
        }
        if (tid < 64) red[tid] = (tid < 50) ? kl : 0.0;
        __syncthreads();
        for (int o = 32; o; o >>= 1) {
            if (tid < o) red[tid] += red[tid + o];
            __syncthreads();
        }
        if (tid == 0) klacc += red[0];
        __syncthreads();
        if (tid < 50) { eprev[tid] = mu; g_etas[t * K_ + tid] = mu; }
        __syncthreads();
    }
    if (tid == 0) atomicAdd(&g_acc[ACC_KLE], klacc);
}

// ================= activation 1: + bias + eta tail + tanh =================
__global__ void k_act1(const float* __restrict__ b1, const float* __restrict__ W1,
                       const int* __restrict__ times) {
    int idx = blockIdx.x * blockDim.x + threadIdx.x;
    if (idx >= B_ * TH_) return;
    int b = idx / TH_, j = idx % TH_;
    float v = g_h1pre[idx] + b1[j];
    const float* e = g_etas + times[b] * K_;
    const float* wtail = W1 + j * (V_ + K_) + V_;
#pragma unroll 10
    for (int k = 0; k < K_; k++) v += e[k] * wtail[k];
    g_h1[idx] = tanhf(v);
}

__global__ void k_act2(const float* __restrict__ b2) {
    int idx = blockIdx.x * blockDim.x + threadIdx.x;
    if (idx >= B_ * TH_) return;
    g_h2[idx] = tanhf(g_h2pre[idx] + b2[idx % TH_]);
}

// ================= mu/ls heads (merged): gridDim.y selects =================
__global__ void k_muls(const float* __restrict__ Wm, const float* __restrict__ bm,
                       const float* __restrict__ Wl, const float* __restrict__ bl) {
    int sel = blockIdx.y;
    const float* W = sel ? Wl : Wm;
    const float* bias = sel ? bl : bm;
    float* C = sel ? g_ls : g_mu;
    int w = blockIdx.x * 8 + (threadIdx.x >> 5);
    int lane = threadIdx.x & 31;
    int nw = gridDim.x * 8;
    for (int idx = w; idx < B_ * K_; idx += nw) {
        int m = idx / K_, n = idx % K_;
        const float* a = g_h2 + m * TH_;
        const float* b = W + n * TH_;
        float s = 0.f;
        for (int k = lane; k < TH_; k += 32) s += a[k] * b[k];
        for (int o = 16; o; o >>= 1) s += __shfl_xor_sync(0xffffffffu, s, o);
        if (lane == 0) C[idx] = s + bias[n];
    }
}

// ================= theta softmax + kl_theta =================
__global__ __launch_bounds__(64) void k_theta(const int* __restrict__ times) {
    int b = blockIdx.x, tid = threadIdx.x;
    __shared__ float sf[64];
    __shared__ double sd[64];
    float m = (tid < K_) ? g_mu[b * K_ + tid] : -1e30f;
    sf[tid] = m;
    __syncthreads();
    for (int o = 32; o; o >>= 1) { if (tid < o) sf[tid] = fmaxf(sf[tid], sf[tid + o]); __syncthreads(); }
    float mx = sf[0];
    __syncthreads();
    float e = (tid < K_) ? __expf(m - mx) : 0.f;
    sf[tid] = e;
    __syncthreads();
    for (int o = 32; o; o >>= 1) { if (tid < o) sf[tid] += sf[tid + o]; __syncthreads(); }
    float sum = sf[0];
    if (tid < K_) g_theta[b * K_ + tid] = e / sum;
    double kl = 0.0;
    if (tid < K_) {
        float lsv = g_ls[b * K_ + tid];
        float et = g_etas[times[b] * K_ + tid];
        float d = m - et;
        kl = 0.5 * ((double)((__expf(lsv) + d * d) / (1.0f + 1e-6f)) - 1.0 - (double)lsv);
    }
    sd[tid] = kl;
    __syncthreads();
    for (int o = 32; o; o >>= 1) { if (tid < o) sd[tid] += sd[tid + o]; __syncthreads(); }
    if (tid == 0) atomicAdd(&g_acc[ACC_KLT], sd[0]);
}

// ================= mix + nll (logits buffer holds exp(logit)) =================
#define VC 500
__global__ __launch_bounds__(512) void k_mix(const float* __restrict__ bows) {
    int t = blockIdx.x;
    int tid = threadIdx.x;
    int v = blockIdx.y * VC + tid;
    bool act = (tid < VC);
    int n_t = g_tcount[t];
    __shared__ float inv_s[K_];
    __shared__ float thg[8][K_];
    __shared__ double red[512];
    if (tid < K_) inv_s[tid] = 1.0f / g_sumexp[t * K_ + tid];
    double nllpart = 0.0;
    for (int grp = 0; grp < n_t; grp += 8) {
        int gn = min(8, n_t - grp);
        __syncthreads();
        if (tid < 8 * K_) {
            int g = tid / K_, k = tid % K_;
            thg[g][k] = (g < gn) ? g_theta[g_tdocs[t * B_ + grp + g] * K_ + k] : 0.f;
        }
        __syncthreads();
        if (act) {
            float a[8] = {0, 0, 0, 0, 0, 0, 0, 0};
            const float* erow = g_logits + (size_t)(t * K_) * V_ + v;
            for (int k = 0; k < K_; k++) {
                float ev = erow[(size_t)k * V_] * inv_s[k];
#pragma unroll
                for (int g = 0; g < 8; g++) a[g] += thg[g][k] * ev;
            }
            for (int g = 0; g < gn; g++) {
                int d = g_tdocs[t * B_ + grp + g];
                nllpart -= (double)(logf(a[g] + 1e-6f) * bows[d * V_ + v]);
            }
        }
    }
    red[tid] = nllpart;
    __syncthreads();
    for (int o = 256; o; o >>= 1) {
        if (tid < o) red[tid] += red[tid + o];
        __syncthreads();
    }
    if (tid == 0) atomicAdd(&g_acc[ACC_NLL], red[0]);
}

// ================= final combine =================
__global__ void k_final(const int* __restrict__ nd, float* __restrict__ out, int out_size) {
    if (threadIdx.x != 0 || blockIdx.x != 0) return;
    double coeff = (double)nd[0] / (double)B_;
    double nll_s = g_acc[ACC_NLL] * coeff;
    double kth   = g_acc[ACC_KLT] * coeff;
    double kla   = g_acc[ACC_KLA];
    double kle   = g_acc[ACC_KLE];
    double nelbo = nll_s + kla + kle + kth;
    double vals[5] = {nelbo, nll_s, kla, kle, kth};
    for (int i = 0; i < 5 && i < out_size; i++) out[i] = (float)vals[i];
}

// ================= host launcher =================
extern "C" void kernel_launch(void* const* d_in, const int* in_sizes, int n_in,
                              void* d_out, int out_size) {
    const float* mu_q  = (const float*)d_in[0];
    const float* lsq   = (const float*)d_in[1];
    const float* slc   = (const float*)d_in[2];
    const float* rho   = (const float*)d_in[3];
    const float* W1    = (const float*)d_in[4];
    const float* b1    = (const float*)d_in[5];
    const float* W2    = (const float*)d_in[6];
    const float* b2    = (const float*)d_in[7];
    const float* muW   = (const float*)d_in[8];
    const float* mub   = (const float*)d_in[9];
    const float* lsW   = (const float*)d_in[10];
    const float* lsb   = (const float*)d_in[11];
    const float* emW   = (const float*)d_in[12];
    const float* emb   = (const float*)d_in[13];
    const float* Wih   = (const float*)d_in[14];
    const float* Whh   = (const float*)d_in[15];
    const float* bih   = (const float*)d_in[16];
    const float* bhh   = (const float*)d_in[17];
    const float* Wme   = (const float*)d_in[18];
    const float* bme   = (const float*)d_in[19];
    const float* Wle   = (const float*)d_in[20];
    const float* ble   = (const float*)d_in[21];
    const float* bows  = (const float*)d_in[22];
    const float* nbows = (const float*)d_in[23];
    const float* rnn   = (const float*)d_in[24];
    const int*   times = (const int*)d_in[25];
    const int*   ndocs = (const int*)d_in[26];
    float* out = (float*)d_out;

    float *p_xpre, *p_gx, *p_c0, *p_h1pre, *p_h1, *p_h2pre, *p_alpha0, *p_logits, *p_sumexp;
    cudaGetSymbolAddress((void**)&p_xpre,   g_xpre);
    cudaGetSymbolAddress((void**)&p_gx,     g_gx);
    cudaGetSymbolAddress((void**)&p_c0,     g_c0);
    cudaGetSymbolAddress((void**)&p_h1pre,  g_h1pre);
    cudaGetSymbolAddress((void**)&p_h1,     g_h1);
    cudaGetSymbolAddress((void**)&p_h2pre,  g_h2pre);
    cudaGetSymbolAddress((void**)&p_alpha0, g_alpha0);
    cudaGetSymbolAddress((void**)&p_logits, g_logits);
    cudaGetSymbolAddress((void**)&p_sumexp, g_sumexp);

    const int LSTM_SMEM = (100 * EH_ + 2 * EH_) * 4;   // ~81.6 KB
    cudaFuncSetAttribute(k_lstm, cudaFuncAttributeMaxDynamicSharedMemorySize, LSTM_SMEM);

    // 0. prep: zeros + alpha0 pack + tlist + c0 = Wih@emb + bih + bhh
    k_prep<<<40, 256>>>(times, Wih, emb, bih, bhh, mu_q);
    // 1. kl_alpha
    k_klalpha<<<(K_ * T_ * R_ + 255) / 256, 256>>>(mu_q, lsq, slc);
    // 2. xpre = rnn @ emW^T   (25x200, K=10000, splitK atomic)
    gemm128<<<dim3(1, 2, 16), 256>>>(rnn, V_, emW, V_, p_xpre, T_, EH_, V_, nullptr, nullptr, 1);
    // 3. gx = xpre @ Wih^T + c0  (25x800, K=200)
    gemm128<<<dim3(1, 7, 1), 256>>>(p_xpre, EH_, Wih, EH_, p_gx, T_, 4 * EH_, EH_, p_c0, nullptr, 0);
    // 4. LSTM recurrence (8-CTA cluster)
    k_lstm<<<8, 256, LSTM_SMEM>>>(Whh);
    // 5. eta projection + scan
    k_etaproj<<<T_, 128>>>(Wme, bme, Wle, ble);
    k_etascan<<<1, 128>>>(Wme, Wle);
    // 6. theta MLP
    gemm128<<<dim3(1, 7, 21), 256>>>(nbows, V_, W1, V_ + K_, p_h1pre, B_, TH_, V_, nullptr, nullptr, 1);
    k_act1<<<(B_ * TH_ + 255) / 256, 256>>>(b1, W1, times);
    gemm128<<<dim3(1, 7, 4), 256>>>(p_h1, TH_, W2, TH_, p_h2pre, B_, TH_, TH_, nullptr, nullptr, 1);
    k_act2<<<(B_ * TH_ + 255) / 256, 256>>>(b2);
    k_muls<<<dim3(25, 2), 256>>>(muW, mub, lsW, lsb);
    k_theta<<<B_, 64>>>(times);
    // 7. beta logits: exp-store + fused row expsum  (1250x10000, K=128)
    gemm128<<<dim3(10, 79, 1), 256>>>(p_alpha0, R_, rho, R_, p_logits, T_ * K_, V_, R_,
                                      nullptr, p_sumexp, 0);
    // 8. mix + nll
    k_mix<<<dim3(T_, V_ / VC), 512>>>(bows);
    // 9. combine
    k_final<<<1, 1>>>(ndocs, out, out_size);
}

// round 4
// speedup vs baseline: 1.2258x; 1.2258x over previous
#include <cuda_runtime.h>
#include <cuda_bf16.h>
#include <math.h>

// ---------------- problem dims (fixed) ----------------
#define S_ 4
#define K_ 50
#define T_ 25
#define R_ 128
#define V_ 10000
#define TH_ 800
#define EH_ 200
#define B_ 128
#define DELTA_ 0.005

#define ACC_KLA 0
#define ACC_KLE 1
#define ACC_KLT 2
#define ACC_NLL 3

// ---------------- device scratch ----------------
__device__ double g_acc[8];
__device__ float  g_xpre[T_ * EH_];
__device__ float  g_gx[T_ * 4 * EH_];
__device__ float  g_c0[4 * EH_];
__device__ float  g_hseq[T_ * EH_];
__device__ float  g_proj[T_ * 100];
__device__ float  g_etas[T_ * K_];
__device__ float  g_h1pre[B_ * TH_];
__device__ float  g_h1[B_ * TH_];
__device__ float  g_h2pre[B_ * TH_];
__device__ float  g_h2[B_ * TH_];
__device__ float  g_mu[B_ * K_];
__device__ float  g_ls[B_ * K_];
__device__ float  g_theta[B_ * K_];
__device__ float  g_alpha0[T_ * K_ * R_];
__device__ float  g_logits[T_ * K_ * V_];   // holds exp(logit)
__device__ float  g_sumexp[T_ * K_];
__device__ float  g_gates[2][4 * EH_];
__device__ int    g_tcount[T_];
__device__ int    g_tdocs[T_ * B_];

__device__ __forceinline__ float sigf(float x) { return 1.f / (1.f + __expf(-x)); }

// ================= k_prep: zero + alpha0 transpose + tlist + c0 =================
__global__ void k_prep(const int* __restrict__ times, const float* __restrict__ Wih,
                       const float* __restrict__ emb, const float* __restrict__ bih,
                       const float* __restrict__ bhh, const float* __restrict__ mu) {
    int blk = blockIdx.x, tid = threadIdx.x;
    if (blk == 0) {
        if (tid < 8) g_acc[tid] = 0.0;
        if (tid < T_) g_tcount[tid] = 0;
        for (int i = tid; i < T_ * K_; i += 256) g_sumexp[i] = 0.f;
        __syncthreads();
        if (tid < B_) {
            int t = times[tid];
            int p = atomicAdd(&g_tcount[t], 1);
            g_tdocs[t * B_ + p] = tid;
        }
    } else if (blk < 32) {
        for (int idx = (blk - 1) * 256 + tid; idx < T_ * K_ * R_; idx += 31 * 256) {
            int r = idx % R_;
            int k = (idx / R_) % K_;
            int t = idx / (R_ * K_);
            g_alpha0[idx] = mu[(k * T_ + t) * R_ + r];
        }
        for (int idx = (blk - 1) * 256 + tid; idx < B_ * TH_; idx += 31 * 256) {
            g_h1pre[idx] = 0.f;
            g_h2pre[idx] = 0.f;
        }
    } else {
        int w = (blk - 32) * 8 + (tid >> 5), lane = tid & 31;
        for (int g = w; g < 4 * EH_; g += 64) {
            const float* row = Wih + g * EH_;
            float s = 0.f;
            for (int e = lane; e < EH_; e += 32) s += row[e] * emb[e];
            for (int o = 16; o; o >>= 1) s += __shfl_xor_sync(0xffffffffu, s, o);
            if (lane == 0) g_c0[g] = s + bih[g] + bhh[g];
        }
    }
}

// ================= gemm128 body: 128x128 tile, 8x8/thread, reg prefetch =================
__device__ __forceinline__ void gemm128_body(
    const float* __restrict__ A, int lda,
    const float* __restrict__ B, int ldb,
    float* __restrict__ C, int M, int N, int K,
    const float* __restrict__ bias, float* __restrict__ expsum, int atomic_out,
    int bx, int by, int bz, int splitK)
{
    __shared__ float As[8][132];
    __shared__ float Bs[8][132];
    int tid = threadIdx.x;
    int tx = tid & 15, ty = tid >> 4;
    int m0 = bx * 128, n0 = by * 128;
    int kc = ((K + splitK - 1) / splitK + 7) & ~7;
    int kbeg = bz * kc;
    int kend = min(K, kbeg + kc);
    if (kbeg >= kend) return;
    int lr = tid >> 1;
    int lk = (tid & 1) * 4;
    bool mok = (m0 + lr) < M;
    bool nok = (n0 + lr) < N;
    const float* Ar = A + (size_t)(m0 + lr) * lda;
    const float* Br = B + (size_t)(n0 + lr) * ldb;
    float2 pa0, pa1, pb0, pb1;
    {
        int kg = kbeg + lk;
        float2 z = make_float2(0.f, 0.f);
        pa0 = mok ? *(const float2*)(Ar + kg) : z;
        pa1 = mok ? *(const float2*)(Ar + kg + 2) : z;
        pb0 = nok ? *(const float2*)(Br + kg) : z;
        pb1 = nok ? *(const float2*)(Br + kg + 2) : z;
    }
    float acc[8][8];
#pragma unroll
    for (int i = 0; i < 8; i++)
#pragma unroll
        for (int j = 0; j < 8; j++) acc[i][j] = 0.f;

    for (int k0 = kbeg; k0 < kend; k0 += 8) {
        As[lk + 0][lr] = pa0.x; As[lk + 1][lr] = pa0.y; As[lk + 2][lr] = pa1.x; As[lk + 3][lr] = pa1.y;
        Bs[lk + 0][lr] = pb0.x; Bs[lk + 1][lr] = pb0.y; Bs[lk + 2][lr] = pb1.x; Bs[lk + 3][lr] = pb1.y;
        __syncthreads();
        int kn = k0 + 8;
        if (kn < kend) {
            int kg = kn + lk;
            float2 z = make_float2(0.f, 0.f);
            pa0 = mok ? *(const float2*)(Ar + kg) : z;
            pa1 = mok ? *(const float2*)(Ar + kg + 2) : z;
            pb0 = nok ? *(const float2*)(Br + kg) : z;
            pb1 = nok ? *(const float2*)(Br + kg + 2) : z;
        }
#pragma unroll
        for (int kk = 0; kk < 8; kk++) {
            float4 a4 = *(const float4*)&As[kk][ty * 8];
            float4 a5 = *(const float4*)&As[kk][ty * 8 + 4];
            float4 b4 = *(const float4*)&Bs[kk][tx * 8];
            float4 b5 = *(const float4*)&Bs[kk][tx * 8 + 4];
            float a[8] = {a4.x, a4.y, a4.z, a4.w, a5.x, a5.y, a5.z, a5.w};
            float b[8] = {b4.x, b4.y, b4.z, b4.w, b5.x, b5.y, b5.z, b5.w};
#pragma unroll
            for (int i = 0; i < 8; i++)
#pragma unroll
                for (int j = 0; j < 8; j++) acc[i][j] = fmaf(a[i], b[j], acc[i][j]);
        }
        __syncthreads();
    }

    int lane = tid & 31;
#pragma unroll
    for (int i = 0; i < 8; i++) {
        int m = m0 + ty * 8 + i;
        if (m >= M) continue;
        float vrow[8];
#pragma unroll
        for (int j = 0; j < 8; j++) {
            float v = acc[i][j];
            int n = n0 + tx * 8 + j;
            if (bias && n < N) v += bias[n];
            vrow[j] = v;
        }
        if (expsum) {
            float rs = 0.f;
#pragma unroll
            for (int j = 0; j < 8; j++) {
                int n = n0 + tx * 8 + j;
                float e = (n < N) ? __expf(vrow[j]) : 0.f;
                vrow[j] = e;
                rs += e;
            }
            for (int o = 8; o; o >>= 1) rs += __shfl_xor_sync(0xffffffffu, rs, o);
            if ((lane & 15) == 0) atomicAdd(&expsum[m], rs);
        }
        float* crow = C + (size_t)m * N;
        int n = n0 + tx * 8;
        if (atomic_out) {
#pragma unroll
            for (int j = 0; j < 8; j++)
                if (n + j < N) atomicAdd(&crow[n + j], vrow[j]);
        } else {
            if (n + 7 < N) {
                *(float4*)&crow[n] = make_float4(vrow[0], vrow[1], vrow[2], vrow[3]);
                *(float4*)&crow[n + 4] = make_float4(vrow[4], vrow[5], vrow[6], vrow[7]);
            } else {
                for (int j = 0; j < 8; j++)
                    if (n + j < N) crow[n + j] = vrow[j];
            }
        }
    }
}

__global__ __launch_bounds__(256, 2) void gemm128(
    const float* __restrict__ A, int lda, const float* __restrict__ B, int ldb,
    float* __restrict__ C, int M, int N, int K,
    const float* __restrict__ bias, float* __restrict__ expsum, int atomic_out) {
    gemm128_body(A, lda, B, ldb, C, M, N, K, bias, expsum, atomic_out,
                 blockIdx.x, blockIdx.y, blockIdx.z, gridDim.z);
}

// ================= kl_alpha body (inline 4x4 slogdet) =================
__device__ __forceinline__ void klalpha_body(const float* __restrict__ mu,
                                             const float* __restrict__ ls,
                                             const float* __restrict__ slc, int blk) {
    __shared__ double pst[10];
    __shared__ double redk[256];
    if (threadIdx.x == 0) {
        double M0[4][4], Mt[4][4];
        for (int i = 0; i < 4; i++)
            for (int j = 0; j < 4; j++) {
                double v = (double)slc[i * 4 + j];
                M0[i][j] = exp(v);
                Mt[i][j] = DELTA_ * v;
            }
        for (int which = 0; which < 2; which++) {
            double lu[4][4];
            for (int i = 0; i < 4; i++)
                for (int j = 0; j < 4; j++) lu[i][j] = which ? Mt[i][j] : M0[i][j];
            double ld = 0.0;
            for (int i = 0; i < 4; i++) {
                int p = i;
                for (int r = i + 1; r < 4; r++)
                    if (fabs(lu[r][i]) > fabs(lu[p][i])) p = r;
                if (p != i)
                    for (int c = 0; c < 4; c++) { double t = lu[i][c]; lu[i][c] = lu[p][c]; lu[p][c] = t; }
                ld += log(fabs(lu[i][i]));
                for (int r = i + 1; r < 4; r++) {
                    double f = lu[r][i] / lu[i][i];
                    for (int c = i; c < 4; c++) lu[r][c] -= f * lu[i][c];
                }
            }
            pst[which] = ld;
        }
        for (int s = 0; s < 4; s++) { pst[2 + s] = M0[s][s]; pst[6 + s] = Mt[s][s]; }
    }
    __syncthreads();
    int idx = blk * 256 + threadIdx.x;
    double term = 0.0;
    if (idx < K_ * T_ * R_) {
        int r = idx % R_;
        int t = (idx / R_) % T_;
        int k = idx / (R_ * T_);
        double ldp = (t == 0) ? pst[0] : pst[1];
        const double* dp = (t == 0) ? (pst + 2) : (pst + 6);
        double ldq = 0.0, tr = 0.0, quad = 0.0;
        for (int s = 0; s < 4; s++) {
            int off = ((s * K_ + k) * T_ + t) * R_ + r;
            float lsv = ls[off];
            float inv = __expf(-lsv);
            ldq += (double)lsv;
            tr += dp[s] * (double)inv;
            float m = mu[off];
            float d = (t == 0) ? m : (m - mu[off - R_]);
            quad += (double)(d * d) * (double)inv;
        }
        term = ldq - ldp - 4.0 + tr + quad;
    }
    int tid = threadIdx.x;
    redk[tid] = term;
    __syncthreads();
    for (int o = 128; o; o >>= 1) {
        if (tid < o) redk[tid] += redk[tid + o];
        __syncthreads();
    }
    if (tid == 0) atomicAdd(&g_acc[ACC_KLA], redk[0]);
}

// ================= FAT kernel: klalpha ∪ xpre ∪ L1-GEMM ∪ logits-GEMM =================
#define FAT_KLA   625
#define FAT_L1    147    // 1 x 7 x 21
#define FAT_LOG   790    // 10 x 79
#define FAT_XPRE  625    // 5000 warps
__global__ __launch_bounds__(256, 2) void k_fat(
    const float* __restrict__ mu_q, const float* __restrict__ lsq, const float* __restrict__ slc,
    const float* __restrict__ rnn, const float* __restrict__ emW,
    const float* __restrict__ nbows, const float* __restrict__ W1,
    const float* __restrict__ rho)
{
    float* p_h1pre  = g_h1pre;
    float* p_logits = g_logits;
    int b = blockIdx.x;
    if (b < FAT_KLA) {
        klalpha_body(mu_q, lsq, slc, b);
    } else if (b < FAT_KLA + FAT_L1) {
        int q = b - FAT_KLA;             // 0..146 -> by 0..6, bz 0..20
        gemm128_body(nbows, V_, W1, V_ + K_, p_h1pre, B_, TH_, V_,
                     nullptr, nullptr, 1, 0, q % 7, q / 7, 21);
    } else if (b < FAT_KLA + FAT_L1 + FAT_LOG) {
        int q = b - FAT_KLA - FAT_L1;    // 0..789 -> bx 0..9, by 0..78
        gemm128_body(g_alpha0, R_, rho, R_, p_logits, T_ * K_, V_, R_,
                     nullptr, g_sumexp, 0, q % 10, q / 10, 0, 1);
    } else {
        int q = b - FAT_KLA - FAT_L1 - FAT_LOG;  // 0..624
        int w = q * 8 + (threadIdx.x >> 5);      // warp id 0..4999
        int lane = threadIdx.x & 31;
        int t = w / EH_, e = w % EH_;
        const float* a = rnn + (size_t)t * V_;
        const float* wr = emW + (size_t)e * V_;
        float s = 0.f;
        for (int k = lane; k < V_; k += 32) s += a[k] * wr[k];
        for (int o = 16; o; o >>= 1) s += __shfl_xor_sync(0xffffffffu, s, o);
        if (lane == 0) g_xpre[t * EH_ + e] = s;
    }
}

// ================= gx = xpre @ Wih^T + c0 (warp per output) =================
__global__ void k_gx(const float* __restrict__ Wih) {
    int w = blockIdx.x * 8 + (threadIdx.x >> 5);
    int lane = threadIdx.x & 31;
    if (w >= T_ * 4 * EH_) return;
    int t = w / (4 * EH_), g = w % (4 * EH_);
    const float* x = g_xpre + t * EH_;
    const float* row = Wih + g * EH_;
    float s = 0.f;
    for (int e = lane; e < EH_; e += 32) s += row[e] * x[e];
    for (int o = 16; o; o >>= 1) s += __shfl_xor_sync(0xffffffffu, s, o);
    if (lane == 0) g_gx[t * 4 * EH_ + g] = s + g_c0[g];
}

// ================= LSTM recurrence: 8-CTA cluster, Whh persistent in SMEM =================
__global__ __cluster_dims__(8, 1, 1) __launch_bounds__(256)
void k_lstm(const float* __restrict__ Whh) {
    extern __shared__ float sm[];
    float* sW = sm;                 // 100*200
    float* h  = sm + 100 * EH_;     // 200
    float* c  = h + EH_;            // 200
    int tid = threadIdx.x;
    int blk = blockIdx.x;
    int g0 = blk * 100;
    for (int i = tid; i < 100 * EH_; i += 256) sW[i] = Whh[g0 * EH_ + i];
    for (int i = tid; i < EH_; i += 256) { h[i] = 0.f; c[i] = 0.f; }
    __syncthreads();
    int w = tid >> 5, lane = tid & 31;
    for (int t = 0; t < T_; t++) {
        const float* gx = g_gx + t * 4 * EH_ + g0;
        float* gout = g_gates[t & 1];
        for (int g = w; g < 100; g += 8) {
            const float* row = sW + g * EH_;
            float s = 0.f;
            for (int e = lane; e < EH_; e += 32) s += row[e] * h[e];
            for (int o = 16; o; o >>= 1) s += __shfl_xor_sync(0xffffffffu, s, o);
            if (lane == 0) gout[g0 + g] = s + gx[g];
        }
        __threadfence();
        asm volatile("barrier.cluster.arrive.aligned;" ::: "memory");
        asm volatile("barrier.cluster.wait.aligned;" ::: "memory");
        const volatile float* gb = g_gates[t & 1];
        for (int e = tid; e < EH_; e += 256) {
            float iv = gb[e], fv = gb[EH_ + e], gg = gb[2 * EH_ + e], ov = gb[3 * EH_ + e];
            float cc = sigf(fv) * c[e] + sigf(iv) * tanhf(gg);
            c[e] = cc;
            float hh = sigf(ov) * tanhf(cc);
            h[e] = hh;
            if (blk == 0) g_hseq[t * EH_ + e] = hh;
        }
        __syncthreads();
    }
}

// ================= eta projection (parallel over t) =================
__global__ __launch_bounds__(128) void k_etaproj(const float* __restrict__ Wm, const float* __restrict__ bm,
                                                 const float* __restrict__ Wl, const float* __restrict__ bl) {
    int t = blockIdx.x;
    int w = threadIdx.x >> 5, lane = threadIdx.x & 31;
    const float* hrow = g_hseq + t * EH_;
    for (int o = w; o < 100; o += 4) {
        const float* row = (o < 50) ? (Wm + o * (EH_ + K_)) : (Wl + (o - 50) * (EH_ + K_));
        float s = 0.f;
        for (int e = lane; e < EH_; e += 32) s += row[e] * hrow[e];
        for (int off = 16; off; off >>= 1) s += __shfl_xor_sync(0xffffffffu, s, off);
        if (lane == 0) g_proj[t * 100 + o] = s + ((o < 50) ? bm[o] : bl[o - 50]);
    }
}

// ================= eta scan (tiny, only the 50-wide recurrent part) =================
__global__ __launch_bounds__(128) void k_etascan(const float* __restrict__ Wm,
                                                 const float* __restrict__ Wl) {
    __shared__ float sWe[100 * 53];
    __shared__ float eprev[52];
    __shared__ float val[128];
    __shared__ double red[64];
    int tid = threadIdx.x;
    for (int i = tid; i < 100 * 50; i += 128) {
        int r = i / 50, j = i % 50;
        sWe[r * 53 + j] = (r < 50) ? Wm[r * (EH_ + K_) + EH_ + j]
                                   : Wl[(r - 50) * (EH_ + K_) + EH_ + j];
    }
    if (tid < 50) eprev[tid] = 0.f;
    __syncthreads();
    double klacc = 0.0;
    const float LOG_DELTA = logf((float)DELTA_);
    for (int t = 0; t < T_; t++) {
        float acc = 0.f;
        if (tid < 100) {
            acc = g_proj[t * 100 + tid];
            const float* row = &sWe[tid * 53];
#pragma unroll
            for (int j = 0; j < 50; j++) acc = fmaf(row[j], eprev[j], acc);
        }
        val[tid] = acc;
        __syncthreads();
        double kl = 0.0;
        float mu = 0.f;
        if (tid < 50) {
            mu = val[tid];
            float lsv = val[50 + tid];
            float ep = eprev[tid];
            float pls = (t == 0) ? 0.f : LOG_DELTA;
            float den = ((t == 0) ? 1.0f : (float)DELTA_) + 1e-6f;
            float d = mu - ep;
            kl = 0.5 * ((double)((__expf(lsv) + d * d) / den) - 1.0 + (double)pls - (double)lsv);
        }
        if (tid < 64) red[tid] = (tid < 50) ? kl : 0.0;
        __syncthreads();
        for (int o = 32; o; o >>= 1) {
            if (tid < o) red[tid] += red[tid + o];
            __syncthreads();
        }
        if (tid == 0) klacc += red[0];
        __syncthreads();
        if (tid < 50) { eprev[tid] = mu; g_etas[t * K_ + tid] = mu; }
        __syncthreads();
    }
    if (tid == 0) atomicAdd(&g_acc[ACC_KLE], klacc);
}

// ================= activation 1: + bias + eta tail + tanh =================
__global__ void k_act1(const float* __restrict__ b1, const float* __restrict__ W1,
                       const int* __restrict__ times) {
    int idx = blockIdx.x * blockDim.x + threadIdx.x;
    if (idx >= B_ * TH_) return;
    int b = idx / TH_, j = idx % TH_;
    float v = g_h1pre[idx] + b1[j];
    const float* e = g_etas + times[b] * K_;
    const float* wtail = W1 + j * (V_ + K_) + V_;
#pragma unroll 10
    for (int k = 0; k < K_; k++) v += e[k] * wtail[k];
    g_h1[idx] = tanhf(v);
}

__global__ void k_act2(const float* __restrict__ b2) {
    int idx = blockIdx.x * blockDim.x + threadIdx.x;
    if (idx >= B_ * TH_) return;
    g_h2[idx] = tanhf(g_h2pre[idx] + b2[idx % TH_]);
}

// ================= mu/ls heads (merged) =================
__global__ void k_muls(const float* __restrict__ Wm, const float* __restrict__ bm,
                       const float* __restrict__ Wl, const float* __restrict__ bl) {
    int sel = blockIdx.y;
    const float* W = sel ? Wl : Wm;
    const float* bias = sel ? bl : bm;
    float* C = sel ? g_ls : g_mu;
    int w = blockIdx.x * 8 + (threadIdx.x >> 5);
    int lane = threadIdx.x & 31;
    int nw = gridDim.x * 8;
    for (int idx = w; idx < B_ * K_; idx += nw) {
        int m = idx / K_, n = idx % K_;
        const float* a = g_h2 + m * TH_;
        const float* b = W + n * TH_;
        float s = 0.f;
        for (int k = lane; k < TH_; k += 32) s += a[k] * b[k];
        for (int o = 16; o; o >>= 1) s += __shfl_xor_sync(0xffffffffu, s, o);
        if (lane == 0) C[idx] = s + bias[n];
    }
}

// ================= theta softmax + kl_theta =================
__global__ __launch_bounds__(64) void k_theta(const int* __restrict__ times) {
    int b = blockIdx.x, tid = threadIdx.x;
    __shared__ float sf[64];
    __shared__ double sd[64];
    float m = (tid < K_) ? g_mu[b * K_ + tid] : -1e30f;
    sf[tid] = m;
    __syncthreads();
    for (int o = 32; o; o >>= 1) { if (tid < o) sf[tid] = fmaxf(sf[tid], sf[tid + o]); __syncthreads(); }
    float mx = sf[0];
    __syncthreads();
    float e = (tid < K_) ? __expf(m - mx) : 0.f;
    sf[tid] = e;
    __syncthreads();
    for (int o = 32; o; o >>= 1) { if (tid < o) sf[tid] += sf[tid + o]; __syncthreads(); }
    float sum = sf[0];
    if (tid < K_) g_theta[b * K_ + tid] = e / sum;
    double kl = 0.0;
    if (tid < K_) {
        float lsv = g_ls[b * K_ + tid];
        float et = g_etas[times[b] * K_ + tid];
        float d = m - et;
        kl = 0.5 * ((double)((__expf(lsv) + d * d) / (1.0f + 1e-6f)) - 1.0 - (double)lsv);
    }
    sd[tid] = kl;
    __syncthreads();
    for (int o = 32; o; o >>= 1) { if (tid < o) sd[tid] += sd[tid + o]; __syncthreads(); }
    if (tid == 0) atomicAdd(&g_acc[ACC_KLT], sd[0]);
}

// ================= mix + nll (logits buffer holds exp(logit)) =================
#define VC 500
__global__ __launch_bounds__(512) void k_mix(const float* __restrict__ bows) {
    int t = blockIdx.x;
    int tid = threadIdx.x;
    int v = blockIdx.y * VC + tid;
    bool act = (tid < VC);
    int n_t = g_tcount[t];
    __shared__ float inv_s[K_];
    __shared__ float thg[8][K_];
    __shared__ double red[512];
    if (tid < K_) inv_s[tid] = 1.0f / g_sumexp[t * K_ + tid];
    double nllpart = 0.0;
    for (int grp = 0; grp < n_t; grp += 8) {
        int gn = min(8, n_t - grp);
        __syncthreads();
        if (tid < 8 * K_) {
            int g = tid / K_, k = tid % K_;
            thg[g][k] = (g < gn) ? g_theta[g_tdocs[t * B_ + grp + g] * K_ + k] : 0.f;
        }
        __syncthreads();
        if (act) {
            float a[8] = {0, 0, 0, 0, 0, 0, 0, 0};
            const float* erow = g_logits + (size_t)(t * K_) * V_ + v;
            for (int k = 0; k < K_; k++) {
                float ev = erow[(size_t)k * V_] * inv_s[k];
#pragma unroll
                for (int g = 0; g < 8; g++) a[g] += thg[g][k] * ev;
            }
            for (int g = 0; g < gn; g++) {
                int d = g_tdocs[t * B_ + grp + g];
                nllpart -= (double)(logf(a[g] + 1e-6f) * bows[d * V_ + v]);
            }
        }
    }
    red[tid] = nllpart;
    __syncthreads();
    for (int o = 256; o; o >>= 1) {
        if (tid < o) red[tid] += red[tid + o];
        __syncthreads();
    }
    if (tid == 0) atomicAdd(&g_acc[ACC_NLL], red[0]);
}

// ================= final combine =================
__global__ void k_final(const int* __restrict__ nd, float* __restrict__ out, int out_size) {
    if (threadIdx.x != 0 || blockIdx.x != 0) return;
    double coeff = (double)nd[0] / (double)B_;
    double nll_s = g_acc[ACC_NLL] * coeff;
    double kth   = g_acc[ACC_KLT] * coeff;
    double kla   = g_acc[ACC_KLA];
    double kle   = g_acc[ACC_KLE];
    double nelbo = nll_s + kla + kle + kth;
    double vals[5] = {nelbo, nll_s, kla, kle, kth};
    for (int i = 0; i < 5 && i < out_size; i++) out[i] = (float)vals[i];
}

// ================= host launcher =================
extern "C" void kernel_launch(void* const* d_in, const int* in_sizes, int n_in,
                              void* d_out, int out_size) {
    const float* mu_q  = (const float*)d_in[0];
    const float* lsq   = (const float*)d_in[1];
    const float* slc   = (const float*)d_in[2];
    const float* rho   = (const float*)d_in[3];
    const float* W1    = (const float*)d_in[4];
    const float* b1    = (const float*)d_in[5];
    const float* W2    = (const float*)d_in[6];
    const float* b2    = (const float*)d_in[7];
    const float* muW   = (const float*)d_in[8];
    const float* mub   = (const float*)d_in[9];
    const float* lsW   = (const float*)d_in[10];
    const float* lsb   = (const float*)d_in[11];
    const float* emW   = (const float*)d_in[12];
    const float* emb   = (const float*)d_in[13];
    const float* Wih   = (const float*)d_in[14];
    const float* Whh   = (const float*)d_in[15];
    const float* bih   = (const float*)d_in[16];
    const float* bhh   = (const float*)d_in[17];
    const float* Wme   = (const float*)d_in[18];
    const float* bme   = (const float*)d_in[19];
    const float* Wle   = (const float*)d_in[20];
    const float* ble   = (const float*)d_in[21];
    const float* bows  = (const float*)d_in[22];
    const float* nbows = (const float*)d_in[23];
    const float* rnn   = (const float*)d_in[24];
    const int*   times = (const int*)d_in[25];
    const int*   ndocs = (const int*)d_in[26];
    float* out = (float*)d_out;

    float *p_h1, *p_h2pre;
    cudaGetSymbolAddress((void**)&p_h1,    g_h1);
    cudaGetSymbolAddress((void**)&p_h2pre, g_h2pre);

    const int LSTM_SMEM = (100 * EH_ + 2 * EH_) * 4;   // ~81.6 KB
    cudaFuncSetAttribute(k_lstm, cudaFuncAttributeMaxDynamicSharedMemorySize, LSTM_SMEM);

    // 1. prep: zeros + alpha0 pack + tlist + c0
    k_prep<<<40, 256>>>(times, Wih, emb, bih, bhh, mu_q);
    // 2. FAT: klalpha + theta-L1 GEMM + logits GEMM + xpre, all concurrent
    k_fat<<<FAT_KLA + FAT_L1 + FAT_LOG + FAT_XPRE, 256>>>(mu_q, lsq, slc, rnn, emW,
                                                          nbows, W1, rho);
    // 3. gx = xpre @ Wih^T + c0 (warp per output)
    k_gx<<<(T_ * 4 * EH_ + 7) / 8 / 256 * 256 ? (T_ * 4 * EH_ / 8) : 1, 256>>>(Wih);
    // 4. LSTM recurrence (8-CTA cluster)  <-- ncu-profiled slot
    k_lstm<<<8, 256, LSTM_SMEM>>>(Whh);
    // 5/6. eta projection + scan
    k_etaproj<<<T_, 128>>>(Wme, bme, Wle, ble);
    k_etascan<<<1, 128>>>(Wme, Wle);
    // 7. act1 (h1pre + bias + eta tail, tanh)
    k_act1<<<(B_ * TH_ + 255) / 256, 256>>>(b1, W1, times);
    // 8. L2 GEMM (splitK=8, atomics into zeroed h2pre)
    gemm128<<<dim3(1, 7, 8), 256>>>(p_h1, TH_, W2, TH_, p_h2pre, B_, TH_, TH_, nullptr, nullptr, 1);
    // 9-11. act2, heads, theta
    k_act2<<<(B_ * TH_ + 255) / 256, 256>>>(b2);
    k_muls<<<dim3(25, 2), 256>>>(muW, mub, lsW, lsb);
    k_theta<<<B_, 64>>>(times);
    // 12. mix + nll
    k_mix<<<dim3(T_, V_ / VC), 512>>>(bows);
    // 13. combine
    k_final<<<1, 1>>>(ndocs, out, out_size);
}

// round 5
// speedup vs baseline: 1.2568x; 1.0253x over previous
#include <cuda_runtime.h>
#include <cuda_bf16.h>
#include <math.h>

// ---------------- problem dims (fixed) ----------------
#define S_ 4
#define K_ 50
#define T_ 25
#define R_ 128
#define V_ 10000
#define TH_ 800
#define EH_ 200
#define B_ 128
#define DELTA_ 0.005

#define ACC_KLA 0
#define ACC_KLE 1
#define ACC_KLT 2
#define ACC_NLL 3

// ---------------- device scratch ----------------
__device__ double g_acc[8];
__device__ float  g_xpre[T_ * EH_];
__device__ float  g_c0[4 * EH_];
__device__ float  g_hseq[T_ * EH_];
__device__ float  g_proj[T_ * 100];
__device__ float  g_etas[T_ * K_];
__device__ float  g_h1pre[B_ * TH_];
__device__ float  g_h1[B_ * TH_];
__device__ float  g_h2pre[B_ * TH_];
__device__ float  g_h2[B_ * TH_];
__device__ float  g_mu[B_ * K_];
__device__ float  g_ls[B_ * K_];
__device__ float  g_theta[B_ * K_];
__device__ float  g_alpha0[T_ * K_ * R_];
__device__ float  g_logits[T_ * K_ * V_];   // holds exp(logit)
__device__ float  g_sumexp[T_ * K_];
__device__ int    g_tcount[T_];
__device__ int    g_tdocs[T_ * B_];

__device__ __forceinline__ float sigf(float x) { return 1.f / (1.f + __expf(-x)); }
__device__ __forceinline__ unsigned smem_u32(const void* p) {
    return (unsigned)__cvta_generic_to_shared(p);
}

// ================= prep_a: zeros + per-time doc lists =================
__global__ void k_prep_a(const int* __restrict__ times) {
    int blk = blockIdx.x, tid = threadIdx.x;
    if (blk == 0) {
        if (tid < 8) g_acc[tid] = 0.0;
        if (tid < T_) g_tcount[tid] = 0;
        for (int i = tid; i < T_ * K_; i += 256) g_sumexp[i] = 0.f;
        for (int i = tid; i < T_ * EH_; i += 256) g_xpre[i] = 0.f;
        __syncthreads();
        if (tid < B_) {
            int t = times[tid];
            int p = atomicAdd(&g_tcount[t], 1);
            g_tdocs[t * B_ + p] = tid;
        }
    } else {
        for (int idx = (blk - 1) * 256 + tid; idx < B_ * TH_; idx += 63 * 256) {
            g_h1pre[idx] = 0.f;
            g_h2pre[idx] = 0.f;
        }
    }
}

// ================= prep_b: alpha0 = mu_q_alpha[0] transposed (K,T,R)->(T,K,R) =================
__global__ void k_prep_b(const float* __restrict__ mu) {
    int idx = blockIdx.x * 256 + threadIdx.x;
    if (idx >= T_ * K_ * R_) return;
    int r = idx % R_;
    int k = (idx / R_) % K_;
    int t = idx / (R_ * K_);
    g_alpha0[idx] = mu[(k * T_ + t) * R_ + r];
}

// ================= prep_c: c0 = Wih@emb + bih + bhh =================
__global__ void k_prep_c(const float* __restrict__ Wih, const float* __restrict__ emb,
                         const float* __restrict__ bih, const float* __restrict__ bhh) {
    int w = blockIdx.x * 8 + (threadIdx.x >> 5), lane = threadIdx.x & 31;
    if (w >= 4 * EH_) return;
    const float* row = Wih + w * EH_;
    float s = 0.f;
    for (int e = lane; e < EH_; e += 32) s += row[e] * emb[e];
    for (int o = 16; o; o >>= 1) s += __shfl_xor_sync(0xffffffffu, s, o);
    if (lane == 0) g_c0[w] = s + bih[w] + bhh[w];
}

// ================= gemm128 body: 128x128 tile, 8x8/thread, reg prefetch =================
__device__ __forceinline__ void gemm128_body(
    const float* __restrict__ A, int lda,
    const float* __restrict__ B, int ldb,
    float* __restrict__ C, int M, int N, int K,
    const float* __restrict__ bias, float* __restrict__ expsum, int atomic_out,
    int bx, int by, int bz, int splitK)
{
    __shared__ float As[8][132];
    __shared__ float Bs[8][132];
    int tid = threadIdx.x;
    int tx = tid & 15, ty = tid >> 4;
    int m0 = bx * 128, n0 = by * 128;
    int kc = ((K + splitK - 1) / splitK + 7) & ~7;
    int kbeg = bz * kc;
    int kend = min(K, kbeg + kc);
    if (kbeg >= kend) return;
    int lr = tid >> 1;
    int lk = (tid & 1) * 4;
    bool mok = (m0 + lr) < M;
    bool nok = (n0 + lr) < N;
    const float* Ar = A + (size_t)(m0 + lr) * lda;
    const float* Br = B + (size_t)(n0 + lr) * ldb;
    float2 pa0, pa1, pb0, pb1;
    {
        int kg = kbeg + lk;
        float2 z = make_float2(0.f, 0.f);
        pa0 = mok ? *(const float2*)(Ar + kg) : z;
        pa1 = mok ? *(const float2*)(Ar + kg + 2) : z;
        pb0 = nok ? *(const float2*)(Br + kg) : z;
        pb1 = nok ? *(const float2*)(Br + kg + 2) : z;
    }
    float acc[8][8];
#pragma unroll
    for (int i = 0; i < 8; i++)
#pragma unroll
        for (int j = 0; j < 8; j++) acc[i][j] = 0.f;

    for (int k0 = kbeg; k0 < kend; k0 += 8) {
        As[lk + 0][lr] = pa0.x; As[lk + 1][lr] = pa0.y; As[lk + 2][lr] = pa1.x; As[lk + 3][lr] = pa1.y;
        Bs[lk + 0][lr] = pb0.x; Bs[lk + 1][lr] = pb0.y; Bs[lk + 2][lr] = pb1.x; Bs[lk + 3][lr] = pb1.y;
        __syncthreads();
        int kn = k0 + 8;
        if (kn < kend) {
            int kg = kn + lk;
            float2 z = make_float2(0.f, 0.f);
            pa0 = mok ? *(const float2*)(Ar + kg) : z;
            pa1 = mok ? *(const float2*)(Ar + kg + 2) : z;
            pb0 = nok ? *(const float2*)(Br + kg) : z;
            pb1 = nok ? *(const float2*)(Br + kg + 2) : z;
        }
#pragma unroll
        for (int kk = 0; kk < 8; kk++) {
            float4 a4 = *(const float4*)&As[kk][ty * 8];
            float4 a5 = *(const float4*)&As[kk][ty * 8 + 4];
            float4 b4 = *(const float4*)&Bs[kk][tx * 8];
            float4 b5 = *(const float4*)&Bs[kk][tx * 8 + 4];
            float a[8] = {a4.x, a4.y, a4.z, a4.w, a5.x, a5.y, a5.z, a5.w};
            float b[8] = {b4.x, b4.y, b4.z, b4.w, b5.x, b5.y, b5.z, b5.w};
#pragma unroll
            for (int i = 0; i < 8; i++)
#pragma unroll
                for (int j = 0; j < 8; j++) acc[i][j] = fmaf(a[i], b[j], acc[i][j]);
        }
        __syncthreads();
    }

    int lane = tid & 31;
#pragma unroll
    for (int i = 0; i < 8; i++) {
        int m = m0 + ty * 8 + i;
        if (m >= M) continue;
        float vrow[8];
#pragma unroll
        for (int j = 0; j < 8; j++) {
            float v = acc[i][j];
            int n = n0 + tx * 8 + j;
            if (bias && n < N) v += bias[n];
            vrow[j] = v;
        }
        if (expsum) {
            float rs = 0.f;
#pragma unroll
            for (int j = 0; j < 8; j++) {
                int n = n0 + tx * 8 + j;
                float e = (n < N) ? __expf(vrow[j]) : 0.f;
                vrow[j] = e;
                rs += e;
            }
            for (int o = 8; o; o >>= 1) rs += __shfl_xor_sync(0xffffffffu, rs, o);
            if ((lane & 15) == 0) atomicAdd(&expsum[m], rs);
        }
        float* crow = C + (size_t)m * N;
        int n = n0 + tx * 8;
        if (atomic_out) {
#pragma unroll
            for (int j = 0; j < 8; j++)
                if (n + j < N) atomicAdd(&crow[n + j], vrow[j]);
        } else {
            if (n + 7 < N) {
                *(float4*)&crow[n] = make_float4(vrow[0], vrow[1], vrow[2], vrow[3]);
                *(float4*)&crow[n + 4] = make_float4(vrow[4], vrow[5], vrow[6], vrow[7]);
            } else {
                for (int j = 0; j < 8; j++)
                    if (n + j < N) crow[n + j] = vrow[j];
            }
        }
    }
}

__global__ __launch_bounds__(256, 2) void gemm128(
    const float* __restrict__ A, int lda, const float* __restrict__ B, int ldb,
    float* __restrict__ C, int M, int N, int K,
    const float* __restrict__ bias, float* __restrict__ expsum, int atomic_out) {
    gemm128_body(A, lda, B, ldb, C, M, N, K, bias, expsum, atomic_out,
                 blockIdx.x, blockIdx.y, blockIdx.z, gridDim.z);
}

// ================= kl_alpha body (inline 4x4 slogdet) =================
__device__ __forceinline__ void klalpha_body(const float* __restrict__ mu,
                                             const float* __restrict__ ls,
                                             const float* __restrict__ slc, int blk) {
    __shared__ double pst[10];
    __shared__ double redk[256];
    if (threadIdx.x == 0) {
        double M0[4][4], Mt[4][4];
        for (int i = 0; i < 4; i++)
            for (int j = 0; j < 4; j++) {
                double v = (double)slc[i * 4 + j];
                M0[i][j] = exp(v);
                Mt[i][j] = DELTA_ * v;
            }
        for (int which = 0; which < 2; which++) {
            double lu[4][4];
            for (int i = 0; i < 4; i++)
                for (int j = 0; j < 4; j++) lu[i][j] = which ? Mt[i][j] : M0[i][j];
            double ld = 0.0;
            for (int i = 0; i < 4; i++) {
                int p = i;
                for (int r = i + 1; r < 4; r++)
                    if (fabs(lu[r][i]) > fabs(lu[p][i])) p = r;
                if (p != i)
                    for (int c = 0; c < 4; c++) { double t = lu[i][c]; lu[i][c] = lu[p][c]; lu[p][c] = t; }
                ld += log(fabs(lu[i][i]));
                for (int r = i + 1; r < 4; r++) {
                    double f = lu[r][i] / lu[i][i];
                    for (int c = i; c < 4; c++) lu[r][c] -= f * lu[i][c];
                }
            }
            pst[which] = ld;
        }
        for (int s = 0; s < 4; s++) { pst[2 + s] = M0[s][s]; pst[6 + s] = Mt[s][s]; }
    }
    __syncthreads();
    int idx = blk * 256 + threadIdx.x;
    double term = 0.0;
    if (idx < K_ * T_ * R_) {
        int r = idx % R_;
        int t = (idx / R_) % T_;
        int k = idx / (R_ * T_);
        double ldp = (t == 0) ? pst[0] : pst[1];
        const double* dp = (t == 0) ? (pst + 2) : (pst + 6);
        double ldq = 0.0, tr = 0.0, quad = 0.0;
        for (int s = 0; s < 4; s++) {
            int off = ((s * K_ + k) * T_ + t) * R_ + r;
            float lsv = ls[off];
            float inv = __expf(-lsv);
            ldq += (double)lsv;
            tr += dp[s] * (double)inv;
            float m = mu[off];
            float d = (t == 0) ? m : (m - mu[off - R_]);
            quad += (double)(d * d) * (double)inv;
        }
        term = ldq - ldp - 4.0 + tr + quad;
    }
    int tid = threadIdx.x;
    redk[tid] = term;
    __syncthreads();
    for (int o = 128; o; o >>= 1) {
        if (tid < o) redk[tid] += redk[tid + o];
        __syncthreads();
    }
    if (tid == 0) atomicAdd(&g_acc[ACC_KLA], redk[0]);
}

// ================= FAT kernel: klalpha ∪ L1-GEMM ∪ logits-GEMM ∪ xpre-GEMM =================
#define FAT_KLA   625
#define FAT_L1    147    // 1 x 7 x 21
#define FAT_LOG   790    // 10 x 79
#define FAT_XPRE  32     // 1 x 2 x 16
__global__ __launch_bounds__(256, 2) void k_fat(
    const float* __restrict__ mu_q, const float* __restrict__ lsq, const float* __restrict__ slc,
    const float* __restrict__ rnn, const float* __restrict__ emW,
    const float* __restrict__ nbows, const float* __restrict__ W1,
    const float* __restrict__ rho)
{
    int b = blockIdx.x;
    if (b < FAT_KLA) {
        klalpha_body(mu_q, lsq, slc, b);
    } else if (b < FAT_KLA + FAT_L1) {
        int q = b - FAT_KLA;             // by 0..6, bz 0..20
        gemm128_body(nbows, V_, W1, V_ + K_, g_h1pre, B_, TH_, V_,
                     nullptr, nullptr, 1, 0, q % 7, q / 7, 21);
    } else if (b < FAT_KLA + FAT_L1 + FAT_LOG) {
        int q = b - FAT_KLA - FAT_L1;    // bx 0..9, by 0..78
        gemm128_body(g_alpha0, R_, rho, R_, g_logits, T_ * K_, V_, R_,
                     nullptr, g_sumexp, 0, q % 10, q / 10, 0, 1);
    } else {
        int q = b - FAT_KLA - FAT_L1 - FAT_LOG;   // by 0..1, bz 0..15
        gemm128_body(rnn, V_, emW, V_, g_xpre, T_, EH_, V_,
                     nullptr, nullptr, 1, 0, q % 2, q / 2, 16);
    }
}

// ================= LSTM: 8-CTA cluster, DSMEM h-broadcast, gx in prologue =================
// CTA b owns hidden units [b*25, b*25+25) and their 4 gate rows (local r = q*25+ul).
#define LSTM_SMEM_FLOATS (20000 + 2500 + 400 + 32 + 256 + 128)
__global__ __cluster_dims__(8, 1, 1) __launch_bounds__(256)
void k_lstm(const float* __restrict__ Whh, const float* __restrict__ Wih) {
    extern __shared__ float sm[];
    float* sW    = sm;               // 100 x 200 (rotated rows)
    float* gxs   = sm + 20000;       // 25 x 100
    float* hbuf  = sm + 22500;       // 2 x 200
    float* cst   = sm + 22900;       // 25 (+pad)
    float* part  = sm + 22932;       // 2 x 128
    float* gatev = sm + 23188;       // 100 (+pad)
    int tid = threadIdx.x;
    int rank = blockIdx.x;

    // --- prologue A: xpre + gx (aliases sW region before Whh load) ---
    float* xpre_s = sW;              // 5000
    float* gxh    = sW + 5000;       // 2 x 2500
    for (int i = tid; i < T_ * EH_; i += 256) xpre_s[i] = g_xpre[i];
    __syncthreads();
    if (tid < 200) {
        int r = tid % 100, half = tid / 100;
        int q = r / 25, ul = r % 25;
        int grow = q * EH_ + rank * 25 + ul;
        const float* wr = Wih + (size_t)grow * EH_ + half * 100;
        const float* xs = xpre_s + half * 100;
        float acc[T_];
#pragma unroll
        for (int t = 0; t < T_; t++) acc[t] = (half == 0) ? g_c0[grow] : 0.f;
        for (int e = 0; e < 100; e++) {
            float w = wr[e];
#pragma unroll
            for (int t = 0; t < T_; t++) acc[t] = fmaf(w, xs[t * EH_ + e], acc[t]);
        }
#pragma unroll
        for (int t = 0; t < T_; t++) gxh[half * 2500 + t * 100 + r] = acc[t];
    }
    __syncthreads();
    for (int i = tid; i < 2500; i += 256) gxs[i] = gxh[i] + gxh[2500 + i];
    __syncthreads();
    // --- prologue B: load Whh rows (rotated by 4*r floats) + init state ---
    for (int i = tid; i < 100 * EH_; i += 256) {
        int r = i / EH_, e = i % EH_;
        int q = r / 25, ul = r % 25;
        int grow = q * EH_ + rank * 25 + ul;
        int eph = e + 4 * r; eph %= EH_;
        sW[r * EH_ + eph] = Whh[(size_t)grow * EH_ + e];
    }
    if (tid < 25) cst[tid] = 0.f;
    if (tid < 200) hbuf[tid] = 0.f;   // buf0 only; buf1 fully overwritten by remote stores
    __syncthreads();
    asm volatile("barrier.cluster.arrive.aligned;" ::: "memory");
    asm volatile("barrier.cluster.wait.aligned;" ::: "memory");

    // --- main loop ---
    int r = tid & 127, half = tid >> 7;
    int ebase = (half * 100 + 4 * r) % EH_;
    for (int t = 0; t < T_; t++) {
        float* cur = hbuf + (t & 1) * EH_;
        float* nxt = hbuf + ((t + 1) & 1) * EH_;
        float acc = 0.f;
        if (r < 100) {
            const float* row = sW + r * EH_;
            const float* hs = cur + half * 100;
#pragma unroll
            for (int i = 0; i < 25; i++) {
                int eph = ebase + 4 * i;
                if (eph >= EH_) eph -= EH_;
                float4 w = *(const float4*)&row[eph];
                float4 hv = *(const float4*)&hs[4 * i];
                acc += w.x * hv.x + w.y * hv.y + w.z * hv.z + w.w * hv.w;
            }
        }
        part[half * 128 + r] = acc;
        __syncthreads();
        if (tid < 100) gatev[tid] = part[tid] + part[128 + tid] + gxs[t * 100 + tid];
        __syncthreads();
        if (tid < 25) {
            float iv = gatev[tid], fv = gatev[25 + tid], gg = gatev[50 + tid], ov = gatev[75 + tid];
            float cc = sigf(fv) * cst[tid] + sigf(iv) * tanhf(gg);
            cst[tid] = cc;
            float hh = sigf(ov) * tanhf(cc);
            g_hseq[t * EH_ + rank * 25 + tid] = hh;
            unsigned la = smem_u32(&nxt[rank * 25 + tid]);
#pragma unroll
            for (int k = 0; k < 8; k++) {
                unsigned ra;
                asm volatile("mapa.shared::cluster.u32 %0, %1, %2;" : "=r"(ra) : "r"(la), "r"(k));
                asm volatile("st.shared::cluster.f32 [%0], %1;" :: "r"(ra), "f"(hh) : "memory");
            }
        }
        asm volatile("barrier.cluster.arrive.aligned;" ::: "memory");
        asm volatile("barrier.cluster.wait.aligned;" ::: "memory");
    }
}

// ================= eta projection (parallel over t) =================
__global__ __launch_bounds__(128) void k_etaproj(const float* __restrict__ Wm, const float* __restrict__ bm,
                                                 const float* __restrict__ Wl, const float* __restrict__ bl) {
    int t = blockIdx.x;
    int w = threadIdx.x >> 5, lane = threadIdx.x & 31;
    const float* hrow = g_hseq + t * EH_;
    for (int o = w; o < 100; o += 4) {
        const float* row = (o < 50) ? (Wm + o * (EH_ + K_)) : (Wl + (o - 50) * (EH_ + K_));
        float s = 0.f;
        for (int e = lane; e < EH_; e += 32) s += row[e] * hrow[e];
        for (int off = 16; off; off >>= 1) s += __shfl_xor_sync(0xffffffffu, s, off);
        if (lane == 0) g_proj[t * 100 + o] = s + ((o < 50) ? bm[o] : bl[o - 50]);
    }
}

// ================= eta scan (tiny, only the 50-wide recurrent part) =================
__global__ __launch_bounds__(128) void k_etascan(const float* __restrict__ Wm,
                                                 const float* __restrict__ Wl) {
    __shared__ float sWe[100 * 53];
    __shared__ float eprev[52];
    __shared__ float val[128];
    __shared__ double red[64];
    int tid = threadIdx.x;
    for (int i = tid; i < 100 * 50; i += 128) {
        int r = i / 50, j = i % 50;
        sWe[r * 53 + j] = (r < 50) ? Wm[r * (EH_ + K_) + EH_ + j]
                                   : Wl[(r - 50) * (EH_ + K_) + EH_ + j];
    }
    if (tid < 50) eprev[tid] = 0.f;
    __syncthreads();
    double klacc = 0.0;
    const float LOG_DELTA = logf((float)DELTA_);
    for (int t = 0; t < T_; t++) {
        float acc = 0.f;
        if (tid < 100) {
            acc = g_proj[t * 100 + tid];
            const float* row = &sWe[tid * 53];
#pragma unroll
            for (int j = 0; j < 50; j++) acc = fmaf(row[j], eprev[j], acc);
        }
        val[tid] = acc;
        __syncthreads();
        double kl = 0.0;
        float mu = 0.f;
        if (tid < 50) {
            mu = val[tid];
            float lsv = val[50 + tid];
            float ep = eprev[tid];
            float pls = (t == 0) ? 0.f : LOG_DELTA;
            float den = ((t == 0) ? 1.0f : (float)DELTA_) + 1e-6f;
            float d = mu - ep;
            kl = 0.5 * ((double)((__expf(lsv) + d * d) / den) - 1.0 + (double)pls - (double)lsv);
        }
        if (tid < 64) red[tid] = (tid < 50) ? kl : 0.0;
        __syncthreads();
        for (int o = 32; o; o >>= 1) {
            if (tid < o) red[tid] += red[tid + o];
            __syncthreads();
        }
        if (tid == 0) klacc += red[0];
        __syncthreads();
        if (tid < 50) { eprev[tid] = mu; g_etas[t * K_ + tid] = mu; }
        __syncthreads();
    }
    if (tid == 0) atomicAdd(&g_acc[ACC_KLE], klacc);
}

// ================= act1: smem-staged W1 tail + etas, coalesced =================
__global__ __launch_bounds__(256) void k_act1(const float* __restrict__ b1,
                                              const float* __restrict__ W1,
                                              const int* __restrict__ times) {
    __shared__ float wt[32 * 53];
    __shared__ float eta_s[T_ * K_];
    __shared__ int tms[B_];
    int jc = blockIdx.x * 32;
    int tid = threadIdx.x;
    for (int i = tid; i < 32 * K_; i += 256) {
        int jl = i / K_, k = i % K_;
        wt[jl * 53 + k] = W1[(size_t)(jc + jl) * (V_ + K_) + V_ + k];
    }
    for (int i = tid; i < T_ * K_; i += 256) eta_s[i] = g_etas[i];
    if (tid < B_) tms[tid] = times[tid];
    __syncthreads();
    int jl = tid & 31, b0 = tid >> 5;
    int j = jc + jl;
    float bj = b1[j];
    const float* w = wt + jl * 53;
    for (int b = b0; b < B_; b += 8) {
        const float* e = eta_s + tms[b] * K_;
        float v = g_h1pre[b * TH_ + j] + bj;
#pragma unroll 10
        for (int k = 0; k < K_; k++) v = fmaf(w[k], e[k], v);
        g_h1[b * TH_ + j] = tanhf(v);
    }
}

__global__ void k_act2(const float* __restrict__ b2) {
    int idx = blockIdx.x * blockDim.x + threadIdx.x;
    if (idx >= B_ * TH_) return;
    g_h2[idx] = tanhf(g_h2pre[idx] + b2[idx % TH_]);
}

// ================= mu/ls heads (merged) =================
__global__ void k_muls(const float* __restrict__ Wm, const float* __restrict__ bm,
                       const float* __restrict__ Wl, const float* __restrict__ bl) {
    int sel = blockIdx.y;
    const float* W = sel ? Wl : Wm;
    const float* bias = sel ? bl : bm;
    float* C = sel ? g_ls : g_mu;
    int w = blockIdx.x * 8 + (threadIdx.x >> 5);
    int lane = threadIdx.x & 31;
    int nw = gridDim.x * 8;
    for (int idx = w; idx < B_ * K_; idx += nw) {
        int m = idx / K_, n = idx % K_;
        const float* a = g_h2 + m * TH_;
        const float* b = W + n * TH_;
        float s = 0.f;
        for (int k = lane; k < TH_; k += 32) s += a[k] * b[k];
        for (int o = 16; o; o >>= 1) s += __shfl_xor_sync(0xffffffffu, s, o);
        if (lane == 0) C[idx] = s + bias[n];
    }
}

// ================= theta softmax + kl_theta =================
__global__ __launch_bounds__(64) void k_theta(const int* __restrict__ times) {
    int b = blockIdx.x, tid = threadIdx.x;
    __shared__ float sf[64];
    __shared__ double sd[64];
    float m = (tid < K_) ? g_mu[b * K_ + tid] : -1e30f;
    sf[tid] = m;
    __syncthreads();
    for (int o = 32; o; o >>= 1) { if (tid < o) sf[tid] = fmaxf(sf[tid], sf[tid + o]); __syncthreads(); }
    float mx = sf[0];
    __syncthreads();
    float e = (tid < K_) ? __expf(m - mx) : 0.f;
    sf[tid] = e;
    __syncthreads();
    for (int o = 32; o; o >>= 1) { if (tid < o) sf[tid] += sf[tid + o]; __syncthreads(); }
    float sum = sf[0];
    if (tid < K_) g_theta[b * K_ + tid] = e / sum;
    double kl = 0.0;
    if (tid < K_) {
        float lsv = g_ls[b * K_ + tid];
        float et = g_etas[times[b] * K_ + tid];
        float d = m - et;
        kl = 0.5 * ((double)((__expf(lsv) + d * d) / (1.0f + 1e-6f)) - 1.0 - (double)lsv);
    }
    sd[tid] = kl;
    __syncthreads();
    for (int o = 32; o; o >>= 1) { if (tid < o) sd[tid] += sd[tid + o]; __syncthreads(); }
    if (tid == 0) atomicAdd(&g_acc[ACC_KLT], sd[0]);
}

// ================= mix + nll (logits buffer holds exp(logit)) =================
#define VC 500
__global__ __launch_bounds__(512) void k_mix(const float* __restrict__ bows) {
    int t = blockIdx.x;
    int tid = threadIdx.x;
    int v = blockIdx.y * VC + tid;
    bool act = (tid < VC);
    int n_t = g_tcount[t];
    __shared__ float inv_s[K_];
    __shared__ float thg[8][K_];
    __shared__ double red[512];
    if (tid < K_) inv_s[tid] = 1.0f / g_sumexp[t * K_ + tid];
    double nllpart = 0.0;
    for (int grp = 0; grp < n_t; grp += 8) {
        int gn = min(8, n_t - grp);
        __syncthreads();
        if (tid < 8 * K_) {
            int g = tid / K_, k = tid % K_;
            thg[g][k] = (g < gn) ? g_theta[g_tdocs[t * B_ + grp + g] * K_ + k] : 0.f;
        }
        __syncthreads();
        if (act) {
            float a[8] = {0, 0, 0, 0, 0, 0, 0, 0};
            const float* erow = g_logits + (size_t)(t * K_) * V_ + v;
            for (int k = 0; k < K_; k++) {
                float ev = erow[(size_t)k * V_] * inv_s[k];
#pragma unroll
                for (int g = 0; g < 8; g++) a[g] += thg[g][k] * ev;
            }
            for (int g = 0; g < gn; g++) {
                int d = g_tdocs[t * B_ + grp + g];
                nllpart -= (double)(logf(a[g] + 1e-6f) * bows[d * V_ + v]);
            }
        }
    }
    red[tid] = nllpart;
    __syncthreads();
    for (int o = 256; o; o >>= 1) {
        if (tid < o) red[tid] += red[tid + o];
        __syncthreads();
    }
    if (tid == 0) atomicAdd(&g_acc[ACC_NLL], red[0]);
}

// ================= final combine =================
__global__ void k_final(const int* __restrict__ nd, float* __restrict__ out, int out_size) {
    if (threadIdx.x != 0 || blockIdx.x != 0) return;
    double coeff = (double)nd[0] / (double)B_;
    double nll_s = g_acc[ACC_NLL] * coeff;
    double kth   = g_acc[ACC_KLT] * coeff;
    double kla   = g_acc[ACC_KLA];
    double kle   = g_acc[ACC_KLE];
    double nelbo = nll_s + kla + kle + kth;
    double vals[5] = {nelbo, nll_s, kla, kle, kth};
    for (int i = 0; i < 5 && i < out_size; i++) out[i] = (float)vals[i];
}

// ================= host launcher =================
extern "C" void kernel_launch(void* const* d_in, const int* in_sizes, int n_in,
                              void* d_out, int out_size) {
    const float* mu_q  = (const float*)d_in[0];
    const float* lsq   = (const float*)d_in[1];
    const float* slc   = (const float*)d_in[2];
    const float* rho   = (const float*)d_in[3];
    const float* W1    = (const float*)d_in[4];
    const float* b1    = (const float*)d_in[5];
    const float* W2    = (const float*)d_in[6];
    const float* b2    = (const float*)d_in[7];
    const float* muW   = (const float*)d_in[8];
    const float* mub   = (const float*)d_in[9];
    const float* lsW   = (const float*)d_in[10];
    const float* lsb   = (const float*)d_in[11];
    const float* emW   = (const float*)d_in[12];
    const float* emb   = (const float*)d_in[13];
    const float* Wih   = (const float*)d_in[14];
    const float* Whh   = (const float*)d_in[15];
    const float* bih   = (const float*)d_in[16];
    const float* bhh   = (const float*)d_in[17];
    const float* Wme   = (const float*)d_in[18];
    const float* bme   = (const float*)d_in[19];
    const float* Wle   = (const float*)d_in[20];
    const float* ble   = (const float*)d_in[21];
    const float* bows  = (const float*)d_in[22];
    const float* nbows = (const float*)d_in[23];
    const float* rnn   = (const float*)d_in[24];
    const int*   times = (const int*)d_in[25];
    const int*   ndocs = (const int*)d_in[26];
    float* out = (float*)d_out;

    float *p_h1, *p_h2pre;
    cudaGetSymbolAddress((void**)&p_h1,    g_h1);
    cudaGetSymbolAddress((void**)&p_h2pre, g_h2pre);

    const int LSTM_SMEM = LSTM_SMEM_FLOATS * 4;   // ~93.3 KB
    cudaFuncSetAttribute(k_lstm, cudaFuncAttributeMaxDynamicSharedMemorySize, LSTM_SMEM);

    // 1-3. prep (split so launch #4 = k_fat lands in the ncu slot)
    k_prep_a<<<64, 256>>>(times);
    k_prep_b<<<(T_ * K_ * R_ + 255) / 256, 256>>>(mu_q);
    k_prep_c<<<(4 * EH_ + 7) / 8 / 32 + 1, 256>>>(Wih, emb, bih, bhh);
    // 4. FAT: klalpha + theta-L1 GEMM + logits GEMM + xpre GEMM, concurrent
    k_fat<<<FAT_KLA + FAT_L1 + FAT_LOG + FAT_XPRE, 256>>>(mu_q, lsq, slc, rnn, emW,
                                                          nbows, W1, rho);
    // 5. LSTM (8-CTA cluster, DSMEM broadcast; gx computed in prologue)
    k_lstm<<<8, 256, LSTM_SMEM>>>(Whh, Wih);
    // 6/7. eta projection + scan
    k_etaproj<<<T_, 128>>>(Wme, bme, Wle, ble);
    k_etascan<<<1, 128>>>(Wme, Wle);
    // 8. act1 (smem-staged tail)
    k_act1<<<T_, 256>>>(b1, W1, times);
    // 9. L2 GEMM (splitK=8, atomics into zeroed h2pre)
    gemm128<<<dim3(1, 7, 8), 256>>>(p_h1, TH_, W2, TH_, p_h2pre, B_, TH_, TH_, nullptr, nullptr, 1);
    // 10-12. act2, heads, theta
    k_act2<<<(B_ * TH_ + 255) / 256, 256>>>(b2);
    k_muls<<<dim3(25, 2), 256>>>(muW, mub, lsW, lsb);
    k_theta<<<B_, 64>>>(times);
    // 13. mix + nll
    k_mix<<<dim3(T_, V_ / VC), 512>>>(bows);
    // 14. combine
    k_final<<<1, 1>>>(ndocs, out, out_size);
}

// round 6
// speedup vs baseline: 1.7840x; 1.4195x over previous
#include <cuda_runtime.h>
#include <cuda_bf16.h>
#include <math.h>

// ---------------- problem dims (fixed) ----------------
#define S_ 4
#define K_ 50
#define T_ 25
#define R_ 128
#define V_ 10000
#define TH_ 800
#define EH_ 200
#define B_ 128
#define DELTA_ 0.005

#define ACC_KLA 0
#define ACC_KLE 1
#define ACC_KLT 2
#define ACC_NLL 3

// ---------------- device scratch ----------------
__device__ double g_acc[8];
__device__ double g_pst[10];              // ld_p0, ld_pt, d_p0[4], d_pt[4]
__device__ float  g_xpre[T_ * EH_];
__device__ float  g_c0[4 * EH_];
__device__ float  g_hseq[T_ * EH_];
__device__ float  g_proj[T_ * 100];
__device__ float  g_etas[T_ * K_];
__device__ float  g_h1pre[B_ * TH_];
__device__ float  g_h1[B_ * TH_];
__device__ float  g_h2pre[B_ * TH_];
__device__ float  g_h2[B_ * TH_];
__device__ float  g_mu[B_ * K_];
__device__ float  g_ls[B_ * K_];
__device__ float  g_theta[B_ * K_];
__device__ float  g_alpha0[T_ * K_ * R_];
__device__ float  g_logits[T_ * K_ * V_];   // holds exp(logit)
__device__ float  g_sumexp[T_ * K_];
__device__ int    g_tcount[T_];
__device__ int    g_tdocs[T_ * B_];

__device__ __forceinline__ float sigf(float x) { return 1.f / (1.f + __expf(-x)); }
__device__ __forceinline__ unsigned smem_u32(const void* p) {
    return (unsigned)__cvta_generic_to_shared(p);
}
__device__ __forceinline__ float tf32r(float x) {
    unsigned u;
    asm("cvt.rna.tf32.f32 %0, %1;" : "=r"(u) : "f"(x));
    return __uint_as_float(u);
}
__device__ __forceinline__ void mma_tf32(float c[4], const unsigned a[4], const unsigned b[2]) {
    asm volatile("mma.sync.aligned.m16n8k8.row.col.f32.tf32.tf32.f32 "
                 "{%0,%1,%2,%3}, {%4,%5,%6,%7}, {%8,%9}, {%0,%1,%2,%3};"
                 : "+f"(c[0]), "+f"(c[1]), "+f"(c[2]), "+f"(c[3])
                 : "r"(a[0]), "r"(a[1]), "r"(a[2]), "r"(a[3]), "r"(b[0]), "r"(b[1]));
}

// ================= prep_a: zeros + doc lists + slogdet =================
__global__ void k_prep_a(const int* __restrict__ times, const float* __restrict__ slc) {
    int blk = blockIdx.x, tid = threadIdx.x;
    if (blk == 0) {
        if (tid < 8) g_acc[tid] = 0.0;
        if (tid < T_) g_tcount[tid] = 0;
        for (int i = tid; i < T_ * K_; i += 256) g_sumexp[i] = 0.f;
        for (int i = tid; i < T_ * EH_; i += 256) g_xpre[i] = 0.f;
        __syncthreads();
        if (tid < B_) {
            int t = times[tid];
            int p = atomicAdd(&g_tcount[t], 1);
            g_tdocs[t * B_ + p] = tid;
        }
        if (tid == 255) {
            double M0[4][4], Mt[4][4];
            for (int i = 0; i < 4; i++)
                for (int j = 0; j < 4; j++) {
                    double v = (double)slc[i * 4 + j];
                    M0[i][j] = exp(v);
                    Mt[i][j] = DELTA_ * v;
                }
            for (int which = 0; which < 2; which++) {
                double lu[4][4];
                for (int i = 0; i < 4; i++)
                    for (int j = 0; j < 4; j++) lu[i][j] = which ? Mt[i][j] : M0[i][j];
                double ld = 0.0;
                for (int i = 0; i < 4; i++) {
                    int p = i;
                    for (int r = i + 1; r < 4; r++)
                        if (fabs(lu[r][i]) > fabs(lu[p][i])) p = r;
                    if (p != i)
                        for (int c = 0; c < 4; c++) { double t = lu[i][c]; lu[i][c] = lu[p][c]; lu[p][c] = t; }
                    ld += log(fabs(lu[i][i]));
                    for (int r = i + 1; r < 4; r++) {
                        double f = lu[r][i] / lu[i][i];
                        for (int c = i; c < 4; c++) lu[r][c] -= f * lu[i][c];
                    }
                }
                g_pst[which] = ld;
            }
            for (int s = 0; s < 4; s++) { g_pst[2 + s] = M0[s][s]; g_pst[6 + s] = Mt[s][s]; }
        }
    } else {
        for (int idx = (blk - 1) * 256 + tid; idx < B_ * TH_; idx += 63 * 256) {
            g_h1pre[idx] = 0.f;
            g_h2pre[idx] = 0.f;
        }
    }
}

// ================= prep_b: alpha0 transpose + c0 =================
__global__ void k_prep_b(const float* __restrict__ mu, const float* __restrict__ Wih,
                         const float* __restrict__ emb, const float* __restrict__ bih,
                         const float* __restrict__ bhh) {
    int blk = blockIdx.x, tid = threadIdx.x;
    if (blk < 625) {
        int idx = blk * 256 + tid;
        if (idx < T_ * K_ * R_) {
            int r = idx % R_;
            int k = (idx / R_) % K_;
            int t = idx / (R_ * K_);
            g_alpha0[idx] = mu[(k * T_ + t) * R_ + r];
        }
    } else {
        int w = (blk - 625) * 8 + (tid >> 5), lane = tid & 31;
        if (w >= 4 * EH_) return;
        const float* row = Wih + w * EH_;
        float s = 0.f;
        for (int e = lane; e < EH_; e += 32) s += row[e] * emb[e];
        for (int o = 16; o; o >>= 1) s += __shfl_xor_sync(0xffffffffu, s, o);
        if (lane == 0) g_c0[w] = s + bih[w] + bhh[w];
    }
}

// ================= tf32 tensor-core GEMM body: 128x128 tile =================
// C[m,n] (+)= sum_k A[m*lda+k]*B[n*ldb+k]. 8 warps = 2(M) x 4(N); warp = 64x32.
__device__ __forceinline__ void gemm_tc_body(
    const float* __restrict__ A, int lda,
    const float* __restrict__ B, int ldb,
    float* __restrict__ C, int M, int N, int K,
    float* __restrict__ expsum, int atomic_out,
    int bx, int by, int bz, int splitK)
{
    __shared__ float As[128 * 36];
    __shared__ float Bs[128 * 36];
    int tid = threadIdx.x;
    int m0 = bx * 128, n0 = by * 128;
    int kbeg, kend;
    if (splitK == 1) { kbeg = 0; kend = K; }
    else {
        int kc = ((K + splitK - 1) / splitK + 31) & ~31;
        kbeg = bz * kc;
        kend = min(K, kbeg + kc);
        if (kbeg >= kend) return;
    }
    int srow = tid >> 1;
    int kq = (tid & 1) * 16;
    bool mok = (m0 + srow) < M;
    bool nok = (n0 + srow) < N;
    const float* Ag = A + (size_t)(m0 + srow) * lda;
    const float* Bg = B + (size_t)(n0 + srow) * ldb;
    float* as = &As[srow * 36 + kq];
    float* bs = &Bs[srow * 36 + kq];

    int lane = tid & 31, wid = tid >> 5;
    int wm = (wid >> 2) * 64, wn = (wid & 3) * 32;
    int g = lane >> 2, tg = lane & 3;

    float c[4][4][4];
#pragma unroll
    for (int mi = 0; mi < 4; mi++)
#pragma unroll
        for (int nj = 0; nj < 4; nj++)
#pragma unroll
            for (int q = 0; q < 4; q++) c[mi][nj][q] = 0.f;

    for (int k0 = kbeg; k0 < kend; k0 += 32) {
#pragma unroll
        for (int i = 0; i < 8; i++) {
            int k = k0 + kq + 2 * i;
            bool kok = (k + 1) < kend;
            float2 z = make_float2(0.f, 0.f);
            float2 va = (mok && kok) ? *(const float2*)(Ag + k) : z;
            float2 vb = (nok && kok) ? *(const float2*)(Bg + k) : z;
            as[2 * i] = tf32r(va.x); as[2 * i + 1] = tf32r(va.y);
            bs[2 * i] = tf32r(vb.x); bs[2 * i + 1] = tf32r(vb.y);
        }
        __syncthreads();
#pragma unroll
        for (int kk = 0; kk < 32; kk += 8) {
            unsigned a[4][4], bf[4][2];
#pragma unroll
            for (int mi = 0; mi < 4; mi++) {
                const float* p = &As[(wm + mi * 16 + g) * 36 + kk + tg];
                a[mi][0] = __float_as_uint(p[0]);
                a[mi][1] = __float_as_uint(p[8 * 36]);
                a[mi][2] = __float_as_uint(p[4]);
                a[mi][3] = __float_as_uint(p[8 * 36 + 4]);
            }
#pragma unroll
            for (int nj = 0; nj < 4; nj++) {
                const float* p = &Bs[(wn + nj * 8 + g) * 36 + kk + tg];
                bf[nj][0] = __float_as_uint(p[0]);
                bf[nj][1] = __float_as_uint(p[4]);
            }
#pragma unroll
            for (int mi = 0; mi < 4; mi++)
#pragma unroll
                for (int nj = 0; nj < 4; nj++) mma_tf32(c[mi][nj], a[mi], bf[nj]);
        }
        __syncthreads();
    }

    if (atomic_out) {
#pragma unroll
        for (int mi = 0; mi < 4; mi++) {
            int r0 = m0 + wm + mi * 16 + g;
            int r1 = r0 + 8;
#pragma unroll
            for (int nj = 0; nj < 4; nj++) {
                int cl = n0 + wn + nj * 8 + 2 * tg;
                if (r0 < M) {
                    if (cl < N)     atomicAdd(&C[(size_t)r0 * N + cl],     c[mi][nj][0]);
                    if (cl + 1 < N) atomicAdd(&C[(size_t)r0 * N + cl + 1], c[mi][nj][1]);
                }
                if (r1 < M) {
                    if (cl < N)     atomicAdd(&C[(size_t)r1 * N + cl],     c[mi][nj][2]);
                    if (cl + 1 < N) atomicAdd(&C[(size_t)r1 * N + cl + 1], c[mi][nj][3]);
                }
            }
        }
    } else {
        // exp-store + per-row expsum accumulation
#pragma unroll
        for (int mi = 0; mi < 4; mi++) {
            int r0 = m0 + wm + mi * 16 + g;
            int r1 = r0 + 8;
            float s0 = 0.f, s1 = 0.f;
#pragma unroll
            for (int nj = 0; nj < 4; nj++) {
                int cl = n0 + wn + nj * 8 + 2 * tg;
                bool c0ok = cl < N, c1ok = (cl + 1) < N;
                float e0 = (r0 < M && c0ok) ? __expf(c[mi][nj][0]) : 0.f;
                float e1 = (r0 < M && c1ok) ? __expf(c[mi][nj][1]) : 0.f;
                float e2 = (r1 < M && c0ok) ? __expf(c[mi][nj][2]) : 0.f;
                float e3 = (r1 < M && c1ok) ? __expf(c[mi][nj][3]) : 0.f;
                if (r0 < M && c0ok) C[(size_t)r0 * N + cl] = e0;
                if (r0 < M && c1ok) C[(size_t)r0 * N + cl + 1] = e1;
                if (r1 < M && c0ok) C[(size_t)r1 * N + cl] = e2;
                if (r1 < M && c1ok) C[(size_t)r1 * N + cl + 1] = e3;
                s0 += e0 + e1;
                s1 += e2 + e3;
            }
            s0 += __shfl_xor_sync(0xffffffffu, s0, 1);
            s0 += __shfl_xor_sync(0xffffffffu, s0, 2);
            s1 += __shfl_xor_sync(0xffffffffu, s1, 1);
            s1 += __shfl_xor_sync(0xffffffffu, s1, 2);
            if (tg == 0) {
                if (r0 < M) atomicAdd(&expsum[r0], s0);
                if (r1 < M) atomicAdd(&expsum[r1], s1);
            }
        }
    }
}

// ================= kl_alpha body (fp32 elementwise, pst precomputed) =================
__device__ __forceinline__ void klalpha_body(const float* __restrict__ mu,
                                             const float* __restrict__ ls, int blk) {
    __shared__ double redk[256];
    int idx = blk * 256 + threadIdx.x;
    float term = 0.f;
    if (idx < K_ * T_ * R_) {
        int r = idx % R_;
        int t = (idx / R_) % T_;
        int k = idx / (R_ * T_);
        float ldp = (float)((t == 0) ? g_pst[0] : g_pst[1]);
        int dpo = (t == 0) ? 2 : 6;
        float ldq = 0.f, tr = 0.f, quad = 0.f;
#pragma unroll
        for (int s = 0; s < 4; s++) {
            int off = ((s * K_ + k) * T_ + t) * R_ + r;
            float lsv = ls[off];
            float inv = __expf(-lsv);
            ldq += lsv;
            tr += (float)g_pst[dpo + s] * inv;
            float m = mu[off];
            float d = (t == 0) ? m : (m - mu[off - R_]);
            quad += d * d * inv;
        }
        term = ldq - ldp - 4.0f + tr + quad;
    }
    int tid = threadIdx.x;
    redk[tid] = (double)term;
    __syncthreads();
    for (int o = 128; o; o >>= 1) {
        if (tid < o) redk[tid] += redk[tid + o];
        __syncthreads();
    }
    if (tid == 0) atomicAdd(&g_acc[ACC_KLA], redk[0]);
}

// ================= FAT kernel: logits-TC ∪ L1-TC ∪ xpre-TC ∪ klalpha =================
#define FAT_LOG   790    // bx 0..9, by 0..78
#define FAT_L1    147    // by 0..6, bz 0..20
#define FAT_XPRE  32     // by 0..1, bz 0..15
#define FAT_KLA   625
__global__ __launch_bounds__(256, 2) void k_fat(
    const float* __restrict__ mu_q, const float* __restrict__ lsq,
    const float* __restrict__ rnn, const float* __restrict__ emW,
    const float* __restrict__ nbows, const float* __restrict__ W1,
    const float* __restrict__ rho)
{
    int b = blockIdx.x;
    if (b < FAT_LOG) {
        gemm_tc_body(g_alpha0, R_, rho, R_, g_logits, T_ * K_, V_, R_,
                     g_sumexp, 0, b % 10, b / 10, 0, 1);
    } else if (b < FAT_LOG + FAT_L1) {
        int q = b - FAT_LOG;
        gemm_tc_body(nbows, V_, W1, V_ + K_, g_h1pre, B_, TH_, V_,
                     nullptr, 1, 0, q % 7, q / 7, 21);
    } else if (b < FAT_LOG + FAT_L1 + FAT_XPRE) {
        int q = b - FAT_LOG - FAT_L1;
        gemm_tc_body(rnn, V_, emW, V_, g_xpre, T_, EH_, V_,
                     nullptr, 1, 0, q % 2, q / 2, 16);
    } else {
        klalpha_body(mu_q, lsq, b - FAT_LOG - FAT_L1 - FAT_XPRE);
    }
}

// ================= LSTM: 8-CTA cluster, DSMEM h-broadcast, gx in prologue =================
#define LSTM_SMEM_FLOATS (20000 + 2500 + 400 + 32 + 256 + 128)
__global__ __cluster_dims__(8, 1, 1) __launch_bounds__(256)
void k_lstm(const float* __restrict__ Whh, const float* __restrict__ Wih) {
    extern __shared__ float sm[];
    float* sW    = sm;               // 100 x 200 (rotated rows)
    float* gxs   = sm + 20000;       // 25 x 100
    float* hbuf  = sm + 22500;       // 2 x 200
    float* cst   = sm + 22900;       // 25 (+pad)
    float* part  = sm + 22932;       // 2 x 128
    float* gatev = sm + 23188;       // 100 (+pad)
    int tid = threadIdx.x;
    int rank = blockIdx.x;

    float* xpre_s = sW;
    float* gxh    = sW + 5000;
    for (int i = tid; i < T_ * EH_; i += 256) xpre_s[i] = g_xpre[i];
    __syncthreads();
    if (tid < 200) {
        int r = tid % 100, half = tid / 100;
        int q = r / 25, ul = r % 25;
        int grow = q * EH_ + rank * 25 + ul;
        const float* wr = Wih + (size_t)grow * EH_ + half * 100;
        const float* xs = xpre_s + half * 100;
        float acc[T_];
#pragma unroll
        for (int t = 0; t < T_; t++) acc[t] = (half == 0) ? g_c0[grow] : 0.f;
        for (int e = 0; e < 100; e++) {
            float w = wr[e];
#pragma unroll
            for (int t = 0; t < T_; t++) acc[t] = fmaf(w, xs[t * EH_ + e], acc[t]);
        }
#pragma unroll
        for (int t = 0; t < T_; t++) gxh[half * 2500 + t * 100 + r] = acc[t];
    }
    __syncthreads();
    for (int i = tid; i < 2500; i += 256) gxs[i] = gxh[i] + gxh[2500 + i];
    __syncthreads();
    for (int i = tid; i < 100 * EH_; i += 256) {
        int r = i / EH_, e = i % EH_;
        int q = r / 25, ul = r % 25;
        int grow = q * EH_ + rank * 25 + ul;
        int eph = e + 4 * r; eph %= EH_;
        sW[r * EH_ + eph] = Whh[(size_t)grow * EH_ + e];
    }
    if (tid < 25) cst[tid] = 0.f;
    if (tid < 200) hbuf[tid] = 0.f;
    __syncthreads();
    asm volatile("barrier.cluster.arrive.aligned;" ::: "memory");
    asm volatile("barrier.cluster.wait.aligned;" ::: "memory");

    int r = tid & 127, half = tid >> 7;
    int ebase = (half * 100 + 4 * r) % EH_;
    for (int t = 0; t < T_; t++) {
        float* cur = hbuf + (t & 1) * EH_;
        float* nxt = hbuf + ((t + 1) & 1) * EH_;
        float acc = 0.f;
        if (r < 100) {
            const float* row = sW + r * EH_;
            const float* hs = cur + half * 100;
#pragma unroll
            for (int i = 0; i < 25; i++) {
                int eph = ebase + 4 * i;
                if (eph >= EH_) eph -= EH_;
                float4 w = *(const float4*)&row[eph];
                float4 hv = *(const float4*)&hs[4 * i];
                acc += w.x * hv.x + w.y * hv.y + w.z * hv.z + w.w * hv.w;
            }
        }
        part[half * 128 + r] = acc;
        __syncthreads();
        if (tid < 100) gatev[tid] = part[tid] + part[128 + tid] + gxs[t * 100 + tid];
        __syncthreads();
        if (tid < 25) {
            float iv = gatev[tid], fv = gatev[25 + tid], gg = gatev[50 + tid], ov = gatev[75 + tid];
            float cc = sigf(fv) * cst[tid] + sigf(iv) * tanhf(gg);
            cst[tid] = cc;
            float hh = sigf(ov) * tanhf(cc);
            g_hseq[t * EH_ + rank * 25 + tid] = hh;
            unsigned la = smem_u32(&nxt[rank * 25 + tid]);
#pragma unroll
            for (int k = 0; k < 8; k++) {
                unsigned ra;
                asm volatile("mapa.shared::cluster.u32 %0, %1, %2;" : "=r"(ra) : "r"(la), "r"(k));
                asm volatile("st.shared::cluster.f32 [%0], %1;" :: "r"(ra), "f"(hh) : "memory");
            }
        }
        asm volatile("barrier.cluster.arrive.aligned;" ::: "memory");
        asm volatile("barrier.cluster.wait.aligned;" ::: "memory");
    }
}

// ================= eta projection (parallel over t) =================
__global__ __launch_bounds__(128) void k_etaproj(const float* __restrict__ Wm, const float* __restrict__ bm,
                                                 const float* __restrict__ Wl, const float* __restrict__ bl) {
    int t = blockIdx.x;
    int w = threadIdx.x >> 5, lane = threadIdx.x & 31;
    const float* hrow = g_hseq + t * EH_;
    for (int o = w; o < 100; o += 4) {
        const float* row = (o < 50) ? (Wm + o * (EH_ + K_)) : (Wl + (o - 50) * (EH_ + K_));
        float s = 0.f;
        for (int e = lane; e < EH_; e += 32) s += row[e] * hrow[e];
        for (int off = 16; off; off >>= 1) s += __shfl_xor_sync(0xffffffffu, s, off);
        if (lane == 0) g_proj[t * 100 + o] = s + ((o < 50) ? bm[o] : bl[o - 50]);
    }
}

// ================= eta scan =================
__global__ __launch_bounds__(128) void k_etascan(const float* __restrict__ Wm,
                                                 const float* __restrict__ Wl) {
    __shared__ float sWe[100 * 53];
    __shared__ float eprev[52];
    __shared__ float val[128];
    __shared__ double red[64];
    int tid = threadIdx.x;
    for (int i = tid; i < 100 * 50; i += 128) {
        int r = i / 50, j = i % 50;
        sWe[r * 53 + j] = (r < 50) ? Wm[r * (EH_ + K_) + EH_ + j]
                                   : Wl[(r - 50) * (EH_ + K_) + EH_ + j];
    }
    if (tid < 50) eprev[tid] = 0.f;
    __syncthreads();
    double klacc = 0.0;
    const float LOG_DELTA = logf((float)DELTA_);
    for (int t = 0; t < T_; t++) {
        float acc = 0.f;
        if (tid < 100) {
            acc = g_proj[t * 100 + tid];
            const float* row = &sWe[tid * 53];
#pragma unroll
            for (int j = 0; j < 50; j++) acc = fmaf(row[j], eprev[j], acc);
        }
        val[tid] = acc;
        __syncthreads();
        double kl = 0.0;
        float mu = 0.f;
        if (tid < 50) {
            mu = val[tid];
            float lsv = val[50 + tid];
            float ep = eprev[tid];
            float pls = (t == 0) ? 0.f : LOG_DELTA;
            float den = ((t == 0) ? 1.0f : (float)DELTA_) + 1e-6f;
            float d = mu - ep;
            kl = 0.5 * ((double)((__expf(lsv) + d * d) / den) - 1.0 + (double)pls - (double)lsv);
        }
        if (tid < 64) red[tid] = (tid < 50) ? kl : 0.0;
        __syncthreads();
        for (int o = 32; o; o >>= 1) {
            if (tid < o) red[tid] += red[tid + o];
            __syncthreads();
        }
        if (tid == 0) klacc += red[0];
        __syncthreads();
        if (tid < 50) { eprev[tid] = mu; g_etas[t * K_ + tid] = mu; }
        __syncthreads();
    }
    if (tid == 0) atomicAdd(&g_acc[ACC_KLE], klacc);
}

// ================= act1: smem-staged W1 tail + etas =================
__global__ __launch_bounds__(256) void k_act1(const float* __restrict__ b1,
                                              const float* __restrict__ W1,
                                              const int* __restrict__ times) {
    __shared__ float wt[32 * 53];
    __shared__ float eta_s[T_ * K_];
    __shared__ int tms[B_];
    int jc = blockIdx.x * 32;
    int tid = threadIdx.x;
    for (int i = tid; i < 32 * K_; i += 256) {
        int jl = i / K_, k = i % K_;
        wt[jl * 53 + k] = W1[(size_t)(jc + jl) * (V_ + K_) + V_ + k];
    }
    for (int i = tid; i < T_ * K_; i += 256) eta_s[i] = g_etas[i];
    if (tid < B_) tms[tid] = times[tid];
    __syncthreads();
    int jl = tid & 31, b0 = tid >> 5;
    int j = jc + jl;
    float bj = b1[j];
    const float* w = wt + jl * 53;
    for (int b = b0; b < B_; b += 8) {
        const float* e = eta_s + tms[b] * K_;
        float v = g_h1pre[b * TH_ + j] + bj;
#pragma unroll 10
        for (int k = 0; k < K_; k++) v = fmaf(w[k], e[k], v);
        g_h1[b * TH_ + j] = tanhf(v);
    }
}

__global__ void k_act2(const float* __restrict__ b2) {
    int idx = blockIdx.x * blockDim.x + threadIdx.x;
    if (idx >= B_ * TH_) return;
    g_h2[idx] = tanhf(g_h2pre[idx] + b2[idx % TH_]);
}

// ================= gemm128 (FFMA, for W2 only) =================
__global__ __launch_bounds__(256, 2) void gemm128(
    const float* __restrict__ A, int lda, const float* __restrict__ B, int ldb,
    float* __restrict__ C, int M, int N, int K)
{
    __shared__ float As[8][132];
    __shared__ float Bs[8][132];
    int tid = threadIdx.x;
    int tx = tid & 15, ty = tid >> 4;
    int m0 = blockIdx.x * 128, n0 = blockIdx.y * 128;
    int splitK = gridDim.z;
    int kc = ((K + splitK - 1) / splitK + 7) & ~7;
    int kbeg = blockIdx.z * kc;
    int kend = min(K, kbeg + kc);
    if (kbeg >= kend) return;
    int lr = tid >> 1;
    int lk = (tid & 1) * 4;
    bool mok = (m0 + lr) < M;
    bool nok = (n0 + lr) < N;
    const float* Ar = A + (size_t)(m0 + lr) * lda;
    const float* Br = B + (size_t)(n0 + lr) * ldb;
    float2 pa0, pa1, pb0, pb1;
    {
        int kg = kbeg + lk;
        float2 z = make_float2(0.f, 0.f);
        pa0 = mok ? *(const float2*)(Ar + kg) : z;
        pa1 = mok ? *(const float2*)(Ar + kg + 2) : z;
        pb0 = nok ? *(const float2*)(Br + kg) : z;
        pb1 = nok ? *(const float2*)(Br + kg + 2) : z;
    }
    float acc[8][8];
#pragma unroll
    for (int i = 0; i < 8; i++)
#pragma unroll
        for (int j = 0; j < 8; j++) acc[i][j] = 0.f;
    for (int k0 = kbeg; k0 < kend; k0 += 8) {
        As[lk + 0][lr] = pa0.x; As[lk + 1][lr] = pa0.y; As[lk + 2][lr] = pa1.x; As[lk + 3][lr] = pa1.y;
        Bs[lk + 0][lr] = pb0.x; Bs[lk + 1][lr] = pb0.y; Bs[lk + 2][lr] = pb1.x; Bs[lk + 3][lr] = pb1.y;
        __syncthreads();
        int kn = k0 + 8;
        if (kn < kend) {
            int kg = kn + lk;
            float2 z = make_float2(0.f, 0.f);
            pa0 = mok ? *(const float2*)(Ar + kg) : z;
            pa1 = mok ? *(const float2*)(Ar + kg + 2) : z;
            pb0 = nok ? *(const float2*)(Br + kg) : z;
            pb1 = nok ? *(const float2*)(Br + kg + 2) : z;
        }
#pragma unroll
        for (int kk = 0; kk < 8; kk++) {
            float4 a4 = *(const float4*)&As[kk][ty * 8];
            float4 a5 = *(const float4*)&As[kk][ty * 8 + 4];
            float4 b4 = *(const float4*)&Bs[kk][tx * 8];
            float4 b5 = *(const float4*)&Bs[kk][tx * 8 + 4];
            float a[8] = {a4.x, a4.y, a4.z, a4.w, a5.x, a5.y, a5.z, a5.w};
            float b[8] = {b4.x, b4.y, b4.z, b4.w, b5.x, b5.y, b5.z, b5.w};
#pragma unroll
            for (int i = 0; i < 8; i++)
#pragma unroll
                for (int j = 0; j < 8; j++) acc[i][j] = fmaf(a[i], b[j], acc[i][j]);
        }
        __syncthreads();
    }
#pragma unroll
    for (int i = 0; i < 8; i++) {
        int m = m0 + ty * 8 + i;
        if (m >= M) continue;
#pragma unroll
        for (int j = 0; j < 8; j++) {
            int n = n0 + tx * 8 + j;
            if (n < N) atomicAdd(&C[(size_t)m * N + n], acc[i][j]);
        }
    }
}

// ================= mu/ls heads (merged) =================
__global__ void k_muls(const float* __restrict__ Wm, const float* __restrict__ bm,
                       const float* __restrict__ Wl, const float* __restrict__ bl) {
    int sel = blockIdx.y;
    const float* W = sel ? Wl : Wm;
    const float* bias = sel ? bl : bm;
    float* C = sel ? g_ls : g_mu;
    int w = blockIdx.x * 8 + (threadIdx.x >> 5);
    int lane = threadIdx.x & 31;
    int nw = gridDim.x * 8;
    for (int idx = w; idx < B_ * K_; idx += nw) {
        int m = idx / K_, n = idx % K_;
        const float* a = g_h2 + m * TH_;
        const float* b = W + n * TH_;
        float s = 0.f;
        for (int k = lane; k < TH_; k += 32) s += a[k] * b[k];
        for (int o = 16; o; o >>= 1) s += __shfl_xor_sync(0xffffffffu, s, o);
        if (lane == 0) C[idx] = s + bias[n];
    }
}

// ================= theta softmax + kl_theta =================
__global__ __launch_bounds__(64) void k_theta(const int* __restrict__ times) {
    int b = blockIdx.x, tid = threadIdx.x;
    __shared__ float sf[64];
    __shared__ double sd[64];
    float m = (tid < K_) ? g_mu[b * K_ + tid] : -1e30f;
    sf[tid] = m;
    __syncthreads();
    for (int o = 32; o; o >>= 1) { if (tid < o) sf[tid] = fmaxf(sf[tid], sf[tid + o]); __syncthreads(); }
    float mx = sf[0];
    __syncthreads();
    float e = (tid < K_) ? __expf(m - mx) : 0.f;
    sf[tid] = e;
    __syncthreads();
    for (int o = 32; o; o >>= 1) { if (tid < o) sf[tid] += sf[tid + o]; __syncthreads(); }
    float sum = sf[0];
    if (tid < K_) g_theta[b * K_ + tid] = e / sum;
    double kl = 0.0;
    if (tid < K_) {
        float lsv = g_ls[b * K_ + tid];
        float et = g_etas[times[b] * K_ + tid];
        float d = m - et;
        kl = 0.5 * ((double)((__expf(lsv) + d * d) / (1.0f + 1e-6f)) - 1.0 - (double)lsv);
    }
    sd[tid] = kl;
    __syncthreads();
    for (int o = 32; o; o >>= 1) { if (tid < o) sd[tid] += sd[tid + o]; __syncthreads(); }
    if (tid == 0) atomicAdd(&g_acc[ACC_KLT], sd[0]);
}

// ================= mix + nll =================
#define VC 500
__global__ __launch_bounds__(512) void k_mix(const float* __restrict__ bows) {
    int t = blockIdx.x;
    int tid = threadIdx.x;
    int v = blockIdx.y * VC + tid;
    bool act = (tid < VC);
    int n_t = g_tcount[t];
    __shared__ float inv_s[K_];
    __shared__ float thg[8][K_];
    __shared__ double red[512];
    if (tid < K_) inv_s[tid] = 1.0f / g_sumexp[t * K_ + tid];
    double nllpart = 0.0;
    for (int grp = 0; grp < n_t; grp += 8) {
        int gn = min(8, n_t - grp);
        __syncthreads();
        if (tid < 8 * K_) {
            int g = tid / K_, k = tid % K_;
            thg[g][k] = (g < gn) ? g_theta[g_tdocs[t * B_ + grp + g] * K_ + k] : 0.f;
        }
        __syncthreads();
        if (act) {
            float a[8] = {0, 0, 0, 0, 0, 0, 0, 0};
            const float* erow = g_logits + (size_t)(t * K_) * V_ + v;
            for (int k = 0; k < K_; k++) {
                float ev = erow[(size_t)k * V_] * inv_s[k];
#pragma unroll
                for (int g = 0; g < 8; g++) a[g] += thg[g][k] * ev;
            }
            for (int g = 0; g < gn; g++) {
                int d = g_tdocs[t * B_ + grp + g];
                nllpart -= (double)(logf(a[g] + 1e-6f) * bows[d * V_ + v]);
            }
        }
    }
    red[tid] = nllpart;
    __syncthreads();
    for (int o = 256; o; o >>= 1) {
        if (tid < o) red[tid] += red[tid + o];
        __syncthreads();
    }
    if (tid == 0) atomicAdd(&g_acc[ACC_NLL], red[0]);
}

// ================= final combine =================
__global__ void k_final(const int* __restrict__ nd, float* __restrict__ out, int out_size) {
    if (threadIdx.x != 0 || blockIdx.x != 0) return;
    double coeff = (double)nd[0] / (double)B_;
    double nll_s = g_acc[ACC_NLL] * coeff;
    double kth   = g_acc[ACC_KLT] * coeff;
    double kla   = g_acc[ACC_KLA];
    double kle   = g_acc[ACC_KLE];
    double nelbo = nll_s + kla + kle + kth;
    double vals[5] = {nelbo, nll_s, kla, kle, kth};
    for (int i = 0; i < 5 && i < out_size; i++) out[i] = (float)vals[i];
}

// ================= host launcher =================
extern "C" void kernel_launch(void* const* d_in, const int* in_sizes, int n_in,
                              void* d_out, int out_size) {
    const float* mu_q  = (const float*)d_in[0];
    const float* lsq   = (const float*)d_in[1];
    const float* slc   = (const float*)d_in[2];
    const float* rho   = (const float*)d_in[3];
    const float* W1    = (const float*)d_in[4];
    const float* b1    = (const float*)d_in[5];
    const float* W2    = (const float*)d_in[6];
    const float* b2    = (const float*)d_in[7];
    const float* muW   = (const float*)d_in[8];
    const float* mub   = (const float*)d_in[9];
    const float* lsW   = (const float*)d_in[10];
    const float* lsb   = (const float*)d_in[11];
    const float* emW   = (const float*)d_in[12];
    const float* emb   = (const float*)d_in[13];
    const float* Wih   = (const float*)d_in[14];
    const float* Whh   = (const float*)d_in[15];
    const float* bih   = (const float*)d_in[16];
    const float* bhh   = (const float*)d_in[17];
    const float* Wme   = (const float*)d_in[18];
    const float* bme   = (const float*)d_in[19];
    const float* Wle   = (const float*)d_in[20];
    const float* ble   = (const float*)d_in[21];
    const float* bows  = (const float*)d_in[22];
    const float* nbows = (const float*)d_in[23];
    const float* rnn   = (const float*)d_in[24];
    const int*   times = (const int*)d_in[25];
    const int*   ndocs = (const int*)d_in[26];
    float* out = (float*)d_out;

    float *p_h1, *p_h2pre;
    cudaGetSymbolAddress((void**)&p_h1,    g_h1);
    cudaGetSymbolAddress((void**)&p_h2pre, g_h2pre);

    const int LSTM_SMEM = LSTM_SMEM_FLOATS * 4;
    cudaFuncSetAttribute(k_lstm, cudaFuncAttributeMaxDynamicSharedMemorySize, LSTM_SMEM);

    // 1-2. prep
    k_prep_a<<<64, 256>>>(times, slc);
    k_prep_b<<<638, 256>>>(mu_q, Wih, emb, bih, bhh);
    // 3. FAT: logits-TC + L1-TC + xpre-TC + klalpha
    k_fat<<<FAT_LOG + FAT_L1 + FAT_XPRE + FAT_KLA, 256>>>(mu_q, lsq, rnn, emW, nbows, W1, rho);
    // 4. LSTM (profiled slot)
    k_lstm<<<8, 256, LSTM_SMEM>>>(Whh, Wih);
    // 5/6. eta projection + scan
    k_etaproj<<<T_, 128>>>(Wme, bme, Wle, ble);
    k_etascan<<<1, 128>>>(Wme, Wle);
    // 7. act1
    k_act1<<<T_, 256>>>(b1, W1, times);
    // 8. W2 GEMM (FFMA splitK)
    gemm128<<<dim3(1, 7, 8), 256>>>(p_h1, TH_, W2, TH_, p_h2pre, B_, TH_, TH_);
    // 9-11. act2, heads, theta
    k_act2<<<(B_ * TH_ + 255) / 256, 256>>>(b2);
    k_muls<<<dim3(25, 2), 256>>>(muW, mub, lsW, lsb);
    k_theta<<<B_, 64>>>(times);
    // 12. mix + nll
    k_mix<<<dim3(T_, V_ / VC), 512>>>(bows);
    // 13. combine
    k_final<<<1, 1>>>(ndocs, out, out_size);
}